// round 13
// baseline (speedup 1.0000x reference)
#include <cuda_runtime.h>
#include <cuda_fp16.h>
#include <math.h>
#include <stdint.h>

#define NROWS 200000
#define DIN   512
#define DOUT  128
#define NQKV  384
#define BK    32
#define NCHUNKS (DIN / BK)                    // 16
#define MTILE 128
#define NBLK_M ((NROWS + MTILE - 1) / MTILE)  // 1563

#define CHUNK 704
#define SLABS (CHUNK / 32)                    // 22
#define NB    ((NROWS + CHUNK - 1) / CHUNK)   // 285
#define NB4   ((NB + 3) / 4)                  // 72

#define KV_SCALE_INV  (1.0f / 64.0f)

__device__ __half g_Q[(size_t)NROWS * DOUT];
__device__ __half g_K[(size_t)NROWS * DOUT];
__device__ __half g_V[(size_t)NROWS * DOUT];
__device__ float g_KVpart[(size_t)NB * DOUT * DOUT];
__device__ float g_kspart[(size_t)NB * DOUT];
__device__ float g_sub[4 * (DOUT * DOUT + DOUT)];
__device__ __half g_KVhi[DOUT * DOUT];
__device__ __half g_KVlo[DOUT * DOUT];
__device__ __half g_kshi16[DOUT];
__device__ __half g_kslo16[DOUT];

__device__ __half g_Wh[(size_t)DIN * NQKV];

// ---- qkv smem (BK=32, fused) ----
#define A_ROW_B   80
#define A_STAGE_B (MTILE * A_ROW_B)          // 10240
#define BF_ROW_B  784
#define BF_STAGE_B (BK * BF_ROW_B)           // 25088
#define SM_B_OFF  (2 * A_STAGE_B)            // 20480
#define SM_QKV_TOTAL (SM_B_OFF + 2 * BF_STAGE_B)   // 70656

#define KVT_ROW_B  272
#define KVT_TILE_B (32 * KVT_ROW_B)          // 8704

#define OUT_Q_OFF   0
#define OUT_Q_B     (128 * 272)
#define OUT_HI_OFF  (OUT_Q_OFF + OUT_Q_B)
#define OUT_KV_B    (128 * 272)
#define OUT_LO_OFF  (OUT_HI_OFF + OUT_KV_B)
#define OUT_KS_OFF  (OUT_LO_OFF + OUT_KV_B)
#define OUT_SM_TOTAL (OUT_KS_OFF + 256 * 2)  // 104960

static __device__ __forceinline__ uint32_t smem_u32(const void* p) {
    uint32_t a;
    asm("{ .reg .u64 t; cvta.to.shared.u64 t, %1; cvt.u32.u64 %0, t; }" : "=r"(a) : "l"(p));
    return a;
}
static __device__ __forceinline__ void cp16(uint32_t dst, const void* src) {
    asm volatile("cp.async.cg.shared.global [%0], [%1], 16;" :: "r"(dst), "l"(src) : "memory");
}
static __device__ __forceinline__ void cp16z(uint32_t dst, const void* src, int sz) {
    asm volatile("cp.async.cg.shared.global [%0], [%1], 16, %2;"
                 :: "r"(dst), "l"(src), "r"(sz) : "memory");
}
#define CP_COMMIT()  asm volatile("cp.async.commit_group;" ::: "memory")
#define CP_WAIT(N)   asm volatile("cp.async.wait_group %0;" :: "n"(N) : "memory")

static __device__ __forceinline__ void ldsm_x4(uint32_t* r, uint32_t addr) {
    asm volatile("ldmatrix.sync.aligned.m8n8.x4.shared.b16 {%0,%1,%2,%3}, [%4];"
                 : "=r"(r[0]), "=r"(r[1]), "=r"(r[2]), "=r"(r[3]) : "r"(addr));
}
static __device__ __forceinline__ void ldsm_x4_t(uint32_t* r, uint32_t addr) {
    asm volatile("ldmatrix.sync.aligned.m8n8.x4.trans.shared.b16 {%0,%1,%2,%3}, [%4];"
                 : "=r"(r[0]), "=r"(r[1]), "=r"(r[2]), "=r"(r[3]) : "r"(addr));
}
static __device__ __forceinline__ void mma16816h(float* d, const uint32_t* a,
                                                 const uint32_t* b) {
    asm volatile(
        "mma.sync.aligned.m16n8k16.row.col.f32.f16.f16.f32 "
        "{%0,%1,%2,%3}, {%4,%5,%6,%7}, {%8,%9}, {%0,%1,%2,%3};"
        : "+f"(d[0]), "+f"(d[1]), "+f"(d[2]), "+f"(d[3])
        : "r"(a[0]), "r"(a[1]), "r"(a[2]), "r"(a[3]), "r"(b[0]), "r"(b[1]));
}

__device__ __forceinline__ float elu_p1(float x) {
    return x > 0.0f ? x + 1.0f : expf(x);
}
static __device__ __forceinline__ uint32_t packh2(float a, float b) {
    __half2 p = __floats2half2_rn(a, b);
    return *(uint32_t*)&p;
}

__global__ void noop_kernel() {}

// ============================================================================
// Kernel W: fp16 weight conversion into [k][384].
// ============================================================================
__global__ void convert_w(const float* __restrict__ Wq,
                          const float* __restrict__ Wk,
                          const float* __restrict__ Wv)
{
    int idx = blockIdx.x * 256 + threadIdx.x;
    if (idx >= DIN * NQKV) return;
    int k = idx / NQKV;
    int n = idx % NQKV;
    const float* W = (n < 128) ? Wq : (n < 256) ? Wk : Wv;
    g_Wh[idx] = __float2half_rn(W[(size_t)k * DOUT + (n & 127)]);
}

// ============================================================================
// Kernel A (fused, 24 warps): [Q|K|V] = f(h @ [Wq|Wk|Wv]), ONE CTA per m-tile.
// 768 threads, 24 warps (4 wm x 6 wn), warp tile 32x64, BK=32 double-buffered.
// Smaller warp tile -> 64 acc regs -> ~85 regs/thread -> 24 warps resident.
// ============================================================================
__global__ __launch_bounds__(768, 1) void qkv_fused(const float* __restrict__ h)
{
    extern __shared__ __align__(256) unsigned char sm[];
    const uint32_t sbase = smem_u32(sm);

    const int row0  = blockIdx.x * MTILE;
    const int tid   = threadIdx.x;
    const int wid   = tid >> 5;
    const int lane  = tid & 31;

    const int wm = wid & 3;
    const int wn = wid >> 2;          // 0..5
    const int m0 = wm * 32;
    const int n0w = wn * 64;

    // A conversion mapping: first 512 threads; row = tid>>2, seg = (tid&3)*8
    const bool aload = (tid < 512);
    const int arow = tid >> 2;
    const int aseg = (tid & 3) * 8;
    int lrow = row0 + arow;
    if (lrow >= NROWS) lrow = NROWS - 1;
    const float* hrow = h + (size_t)lrow * DIN + aseg;
    const uint32_t a_sts_off = (uint32_t)(arow * A_ROW_B + aseg * 2);

    float acc[2][8][4];
    #pragma unroll
    for (int i = 0; i < 2; i++)
        #pragma unroll
        for (int j = 0; j < 8; j++)
            #pragma unroll
            for (int r = 0; r < 4; r++) acc[i][j][r] = 0.0f;

    const int a_r = (lane & 7) + (lane & 8);
    const int a_c = ((lane >> 4) & 1) * 8;
    const int b_k = (lane & 7) + (lane & 8);
    const int b_n = ((lane >> 4) & 1) * 8;

    auto issue_B = [&](int c, int stage) {
        // 32 rows x 48 c16 = 1536 cp16, 2 per thread
        const size_t src_k0 = (size_t)(c * BK) * NQKV;
        uint32_t dstb = sbase + SM_B_OFF + stage * BF_STAGE_B;
        #pragma unroll
        for (int it = 0; it < 2; it++) {
            int idx = tid + it * 768;
            int r = idx / 48, c16 = idx % 48;
            cp16(dstb + r * BF_ROW_B + c16 * 16,
                 g_Wh + src_k0 + (size_t)r * NQKV + c16 * 8);
        }
        CP_COMMIT();
    };
    auto sts_A = [&](int stage, const float4* v) {
        uint32_t hx[4];
        hx[0] = packh2(v[0].x, v[0].y);
        hx[1] = packh2(v[0].z, v[0].w);
        hx[2] = packh2(v[1].x, v[1].y);
        hx[3] = packh2(v[1].z, v[1].w);
        uint32_t dst = sbase + stage * A_STAGE_B + a_sts_off;
        asm volatile("st.shared.v4.b32 [%0], {%1,%2,%3,%4};" :: "r"(dst),
                     "r"(hx[0]),"r"(hx[1]),"r"(hx[2]),"r"(hx[3]));
    };

    float4 v[2];
    if (aload) {
        v[0] = *(const float4*)(hrow);
        v[1] = *(const float4*)(hrow + 4);
    }
    issue_B(0, 0);
    if (aload) sts_A(0, v);

    for (int c = 0; c < NCHUNKS; c++) {
        const int stage = c & 1;

        if (aload && c + 1 < NCHUNKS) {
            v[0] = *(const float4*)(hrow + (c + 1) * BK);
            v[1] = *(const float4*)(hrow + (c + 1) * BK + 4);
        }
        CP_WAIT(0);
        __syncthreads();
        if (c + 1 < NCHUNKS) issue_B(c + 1, stage ^ 1);

        const uint32_t Ab = sbase + stage * A_STAGE_B;
        const uint32_t Bb = sbase + SM_B_OFF + stage * BF_STAGE_B;
        #pragma unroll
        for (int ks = 0; ks < 2; ks++) {
            const int k0 = ks * 16;
            uint32_t afr[2][4];
            #pragma unroll
            for (int im = 0; im < 2; im++)
                ldsm_x4(afr[im], Ab + (uint32_t)((m0 + im * 16 + a_r) * A_ROW_B +
                                                 (k0 + a_c) * 2));
            // process B in two 32-col halves to cap live registers
            #pragma unroll
            for (int hg = 0; hg < 2; hg++) {
                uint32_t bfr[2][4];
                #pragma unroll
                for (int j2 = 0; j2 < 2; j2++)
                    ldsm_x4_t(bfr[j2], Bb + (uint32_t)((k0 + b_k) * BF_ROW_B +
                              (n0w + (hg * 2 + j2) * 16 + b_n) * 2));
                #pragma unroll
                for (int im = 0; im < 2; im++)
                    #pragma unroll
                    for (int j2 = 0; j2 < 2; j2++) {
                        const int j = (hg * 2 + j2) * 2;
                        mma16816h(acc[im][j + 0], afr[im], &bfr[j2][0]);
                        mma16816h(acc[im][j + 1], afr[im], &bfr[j2][2]);
                    }
            }
        }

        if (aload && c + 1 < NCHUNKS) sts_A(stage ^ 1, v);
    }

    // ---- epilogue: each warp's 64 cols lie within one of Q/K/V ----
    const int g = lane >> 2;
    const int t = lane & 3;

    #pragma unroll
    for (int im = 0; im < 2; im++) {
        const int r0 = row0 + m0 + im * 16 + g;
        const int r1 = r0 + 8;
        #pragma unroll
        for (int j = 0; j < 8; j++) {
            const int col = n0w + j * 8 + t * 2;
            const int which = col >> 7;
            const int lc = col & 127;
            __half* Out = (which == 0) ? g_Q : (which == 1) ? g_K : g_V;
            const bool act = (which < 2);
            float c0 = acc[im][j][0], c1 = acc[im][j][1];
            float c2 = acc[im][j][2], c3 = acc[im][j][3];
            if (act) {
                c0 = elu_p1(c0); c1 = elu_p1(c1);
                c2 = elu_p1(c2); c3 = elu_p1(c3);
            }
            if (r0 < NROWS)
                *(__half2*)(Out + (size_t)r0 * DOUT + lc) = __floats2half2_rn(c0, c1);
            if (r1 < NROWS)
                *(__half2*)(Out + (size_t)r1 * DOUT + lc) = __floats2half2_rn(c2, c3);
        }
    }
}

// ============================================================================
// Kernel B: partial KV = K_chunk^T @ V_chunk via fp16 mma + k_sum via MMA.
// ============================================================================
__global__ __launch_bounds__(256, 2) void kv_mma()
{
    __shared__ __align__(16) unsigned char sm[2 * 2 * KVT_TILE_B];
    const uint32_t sb = smem_u32(sm);

    const int tid  = threadIdx.x;
    const int wid  = tid >> 5;
    const int lane = tid & 31;
    const int m0 = (wid & 3) * 32;
    const int n0 = (wid >> 2) * 64;
    const int wn = wid >> 2;
    const int base = blockIdx.x * CHUNK;

    float acc[2][8][4];
    #pragma unroll
    for (int i = 0; i < 2; i++)
        #pragma unroll
        for (int j = 0; j < 8; j++)
            #pragma unroll
            for (int r = 0; r < 4; r++) acc[i][j][r] = 0.0f;
    float acc_ks[2][4];
    #pragma unroll
    for (int i = 0; i < 2; i++)
        #pragma unroll
        for (int r = 0; r < 4; r++) acc_ks[i][r] = 0.0f;

    const uint32_t b_ones[2] = {0x3C003C00u, 0x3C003C00u};

    auto issue = [&](int it, int stage) {
        #pragma unroll
        for (int q = 0; q < 4; q++) {
            int idx  = tid + q * 256;
            int tile = idx >> 9;
            int row  = (idx >> 4) & 31;
            int c16  = idx & 15;
            int grow = base + it * 32 + row;
            const __half* src = (tile ? g_V : g_K) + (size_t)grow * DOUT + c16 * 8;
            uint32_t dst = sb + stage * 2 * KVT_TILE_B + tile * KVT_TILE_B +
                           row * KVT_ROW_B + c16 * 16;
            cp16z(dst, src, (grow < NROWS) ? 16 : 0);
        }
        CP_COMMIT();
    };

    const int trow = (lane & 7) + (lane & 8);
    const int tcol = ((lane >> 4) & 1) * 8;

    issue(0, 0);

    for (int it = 0; it < SLABS; it++) {
        const int stage = it & 1;
        CP_WAIT(0);
        __syncthreads();
        if (it + 1 < SLABS) issue(it + 1, stage ^ 1);

        const uint32_t Kb = sb + stage * 2 * KVT_TILE_B;
        const uint32_t Vb = Kb + KVT_TILE_B;

        #pragma unroll
        for (int ks = 0; ks < 2; ks++) {
            const int k0 = ks * 16;
            uint32_t afr[2][4];
            #pragma unroll
            for (int im = 0; im < 2; im++) {
                uint32_t t4[4];
                ldsm_x4_t(t4, Kb + (uint32_t)((k0 + trow) * KVT_ROW_B +
                                              (m0 + im * 16 + tcol) * 2));
                afr[im][0] = t4[0]; afr[im][1] = t4[2];
                afr[im][2] = t4[1]; afr[im][3] = t4[3];
            }
            uint32_t bfr[4][4];
            #pragma unroll
            for (int jn = 0; jn < 4; jn++)
                ldsm_x4_t(bfr[jn], Vb + (uint32_t)((k0 + trow) * KVT_ROW_B +
                                                   (n0 + jn * 16 + tcol) * 2));
            #pragma unroll
            for (int im = 0; im < 2; im++)
                #pragma unroll
                for (int jn = 0; jn < 4; jn++) {
                    mma16816h(acc[im][jn * 2 + 0], afr[im], &bfr[jn][0]);
                    mma16816h(acc[im][jn * 2 + 1], afr[im], &bfr[jn][2]);
                }
            if (wn == 0) {
                mma16816h(acc_ks[0], afr[0], b_ones);
                mma16816h(acc_ks[1], afr[1], b_ones);
            }
        }
    }

    float* kvout = g_KVpart + (size_t)blockIdx.x * (DOUT * DOUT);
    const int g = lane >> 2;
    const int t = lane & 3;
    #pragma unroll
    for (int im = 0; im < 2; im++) {
        const int r0 = m0 + im * 16 + g;
        #pragma unroll
        for (int j = 0; j < 8; j++) {
            const int col = n0 + j * 8 + t * 2;
            *(float2*)(kvout + (size_t)r0 * DOUT + col) =
                make_float2(acc[im][j][0], acc[im][j][1]);
            *(float2*)(kvout + (size_t)(r0 + 8) * DOUT + col) =
                make_float2(acc[im][j][2], acc[im][j][3]);
        }
    }
    if (wn == 0 && t == 0) {
        #pragma unroll
        for (int im = 0; im < 2; im++) {
            const int r = m0 + im * 16 + g;
            g_kspart[(size_t)blockIdx.x * DOUT + r]     = acc_ks[im][0];
            g_kspart[(size_t)blockIdx.x * DOUT + r + 8] = acc_ks[im][2];
        }
    }
}

// ============================================================================
// Reduce phase 1: 4 sub-range partial sums. Grid (65, 4).
// ============================================================================
__global__ void reduce1()
{
    const int sub = blockIdx.y;
    const int i = blockIdx.x * blockDim.x + threadIdx.x;
    if (i >= DOUT * DOUT + DOUT) return;
    const int b0 = sub * NB4;
    const int b1 = (b0 + NB4 < NB) ? b0 + NB4 : NB;

    float s0 = 0.0f, s1 = 0.0f, s2 = 0.0f, s3 = 0.0f;
    if (i < DOUT * DOUT) {
        int b = b0;
        for (; b + 3 < b1; b += 4) {
            s0 += g_KVpart[(size_t)(b + 0) * (DOUT * DOUT) + i];
            s1 += g_KVpart[(size_t)(b + 1) * (DOUT * DOUT) + i];
            s2 += g_KVpart[(size_t)(b + 2) * (DOUT * DOUT) + i];
            s3 += g_KVpart[(size_t)(b + 3) * (DOUT * DOUT) + i];
        }
        for (; b < b1; b++) s0 += g_KVpart[(size_t)b * (DOUT * DOUT) + i];
    } else {
        const int j = i - DOUT * DOUT;
        int b = b0;
        for (; b + 3 < b1; b += 4) {
            s0 += g_kspart[(size_t)(b + 0) * DOUT + j];
            s1 += g_kspart[(size_t)(b + 1) * DOUT + j];
            s2 += g_kspart[(size_t)(b + 2) * DOUT + j];
            s3 += g_kspart[(size_t)(b + 3) * DOUT + j];
        }
        for (; b < b1; b++) s0 += g_kspart[(size_t)b * DOUT + j];
    }
    g_sub[sub * (DOUT * DOUT + DOUT) + i] = ((s0 + s1) + (s2 + s3));
}

// ============================================================================
// Reduce phase 2: combine 4 subs, emit fp16 hi/lo KV and ksum.
// ============================================================================
__global__ void reduce2()
{
    const int i = blockIdx.x * blockDim.x + threadIdx.x;
    if (i >= DOUT * DOUT + DOUT) return;
    const int stride = DOUT * DOUT + DOUT;
    float s = (g_sub[i] + g_sub[stride + i]) +
              (g_sub[2 * stride + i] + g_sub[3 * stride + i]);
    if (i < DOUT * DOUT) {
        s *= KV_SCALE_INV;
        __half hi = __float2half_rn(s);
        g_KVhi[i] = hi;
        g_KVlo[i] = __float2half_rn(s - __half2float(hi));
    } else {
        const int j = i - DOUT * DOUT;
        s *= 0.125f;
        __half hi = __float2half_rn(s);
        g_kshi16[j] = hi;
        g_kslo16[j] = __float2half_rn(s - __half2float(hi));
    }
}

// ============================================================================
// Kernel C: out = elu((Q @ KV) / (Q @ ksum)) via fp16 mma. 128-row blocks.
// ============================================================================
__global__ __launch_bounds__(512, 1) void out_mma(float* __restrict__ out)
{
    extern __shared__ __align__(256) unsigned char smo[];
    const uint32_t sb = smem_u32(smo);

    const int tid  = threadIdx.x;
    const int wid  = tid >> 5;
    const int lane = tid & 31;
    const int row0 = blockIdx.x * 128;

    const int m0 = (wid & 3) * 32;
    const int n0 = (wid >> 2) * 32;

    #pragma unroll
    for (int q = 0; q < 4; q++) {
        int idx = tid + q * 512;
        int r = idx >> 4, c16 = idx & 15;
        int grow = row0 + r;
        cp16z(sb + OUT_Q_OFF + r * 272 + c16 * 16,
              g_Q + (size_t)grow * DOUT + c16 * 8,
              (grow < NROWS) ? 16 : 0);
    }
    #pragma unroll
    for (int q = 0; q < 8; q++) {
        int idx = tid + q * 512;
        int part = idx >> 11;
        int rem = idx & 2047;
        int r = rem >> 4, c16 = rem & 15;
        const __half* src = (part ? g_KVlo : g_KVhi) + r * DOUT + c16 * 8;
        cp16(sb + (part ? OUT_LO_OFF : OUT_HI_OFF) + r * 272 + c16 * 16, src);
    }
    CP_COMMIT();
    __half* kss = (__half*)(smo + OUT_KS_OFF);
    if (tid < 128) kss[tid] = g_kshi16[tid];
    else if (tid < 256) kss[tid] = g_kslo16[tid - 128];
    CP_WAIT(0);
    __syncthreads();

    float acc[2][4][4];
    #pragma unroll
    for (int i = 0; i < 2; i++)
        #pragma unroll
        for (int j = 0; j < 4; j++)
            #pragma unroll
            for (int r = 0; r < 4; r++) acc[i][j][r] = 0.0f;
    float acc_z[2][4];
    #pragma unroll
    for (int i = 0; i < 2; i++)
        #pragma unroll
        for (int r = 0; r < 4; r++) acc_z[i][r] = 0.0f;

    const int a_r = (lane & 7) + (lane & 8);
    const int a_c = ((lane >> 4) & 1) * 8;
    const int zcol = lane >> 2;
    const int zk   = (lane & 3) * 2;

    #pragma unroll
    for (int ks = 0; ks < 8; ks++) {
        const int k0 = ks * 16;
        uint32_t afr[2][4];
        #pragma unroll
        for (int im = 0; im < 2; im++)
            ldsm_x4(afr[im], sb + OUT_Q_OFF +
                    (uint32_t)((m0 + im * 16 + a_r) * 272 + (k0 + a_c) * 2));
        #pragma unroll
        for (int part = 0; part < 2; part++) {
            const uint32_t Bb = sb + (part ? OUT_LO_OFF : OUT_HI_OFF);
            uint32_t bfr[2][4];
            #pragma unroll
            for (int jn = 0; jn < 2; jn++)
                ldsm_x4_t(bfr[jn], Bb + (uint32_t)((k0 + a_r) * 272 +
                                                   (n0 + jn * 16 + a_c) * 2));
            #pragma unroll
            for (int im = 0; im < 2; im++)
                #pragma unroll
                for (int jn = 0; jn < 2; jn++) {
                    mma16816h(acc[im][jn * 2 + 0], afr[im], &bfr[jn][0]);
                    mma16816h(acc[im][jn * 2 + 1], afr[im], &bfr[jn][2]);
                }
        }
        uint32_t zb[2] = {0u, 0u};
        if (zcol < 2) {
            const __half* kp = kss + zcol * 128 + k0 + zk;
            zb[0] = *(const uint32_t*)(kp);
            zb[1] = *(const uint32_t*)(kp + 8);
        }
        mma16816h(acc_z[0], afr[0], zb);
        mma16816h(acc_z[1], afr[1], zb);
    }

    const int g = lane >> 2;
    const int t = lane & 3;
    #pragma unroll
    for (int im = 0; im < 2; im++) {
        float den0 = acc_z[im][0] + acc_z[im][1];
        float den1 = acc_z[im][2] + acc_z[im][3];
        den0 = __shfl_sync(0xffffffffu, den0, lane & 28);
        den1 = __shfl_sync(0xffffffffu, den1, lane & 28);
        const float z0 = 8.0f / den0;
        const float z1 = 8.0f / den1;
        const int gr0 = row0 + m0 + im * 16 + g;
        const int gr1 = gr0 + 8;
        #pragma unroll
        for (int j = 0; j < 4; j++) {
            const int col = n0 + j * 8 + t * 2;
            float x0 = acc[im][j][0] * z0;
            float x1 = acc[im][j][1] * z0;
            float x2 = acc[im][j][2] * z1;
            float x3 = acc[im][j][3] * z1;
            x0 = x0 > 0.0f ? x0 : expm1f(x0);
            x1 = x1 > 0.0f ? x1 : expm1f(x1);
            x2 = x2 > 0.0f ? x2 : expm1f(x2);
            x3 = x3 > 0.0f ? x3 : expm1f(x3);
            if (gr0 < NROWS)
                *(float2*)(out + (size_t)gr0 * DOUT + col) = make_float2(x0, x1);
            if (gr1 < NROWS)
                *(float2*)(out + (size_t)gr1 * DOUT + col) = make_float2(x2, x3);
        }
    }
}

// ============================================================================
// Launch
// ============================================================================
extern "C" void kernel_launch(void* const* d_in, const int* in_sizes, int n_in,
                              void* d_out, int out_size)
{
    const float* h  = (const float*)d_in[0];
    const float* Wq = (const float*)d_in[1];
    const float* Wk = (const float*)d_in[2];
    const float* Wv = (const float*)d_in[3];
    float* out = (float*)d_out;

    cudaFuncSetAttribute(qkv_fused, cudaFuncAttributeMaxDynamicSharedMemorySize, SM_QKV_TOTAL);
    cudaFuncSetAttribute(out_mma, cudaFuncAttributeMaxDynamicSharedMemorySize, OUT_SM_TOTAL);

    convert_w<<<(DIN * NQKV + 255) / 256, 256>>>(Wq, Wk, Wv);   // idx 0
    noop_kernel<<<1, 32>>>();                                    // idx 1
    noop_kernel<<<1, 32>>>();                                    // idx 2

    qkv_fused<<<NBLK_M, 768, SM_QKV_TOTAL>>>(h);                 // idx 3 (profiled)

    kv_mma<<<NB, 256>>>();

    dim3 gridR1((DOUT * DOUT + DOUT + 255) / 256, 4);
    reduce1<<<gridR1, 256>>>();
    reduce2<<<(DOUT * DOUT + DOUT + 255) / 256, 256>>>();

    out_mma<<<(NROWS + 127) / 128, 512, OUT_SM_TOTAL>>>(out);
}

// round 14
// speedup vs baseline: 1.2500x; 1.2500x over previous
#include <cuda_runtime.h>
#include <cuda_fp16.h>
#include <math.h>
#include <stdint.h>

#define NROWS 200000
#define DIN   512
#define DOUT  128
#define NQKV  384
#define BK    32
#define NCHUNKS (DIN / BK)                    // 16
#define MTILE 64
#define NBLK_M ((NROWS + MTILE - 1) / MTILE)  // 3125

#define CHUNK 704
#define SLABS (CHUNK / 32)                    // 22
#define NB    ((NROWS + CHUNK - 1) / CHUNK)   // 285
#define NB4   ((NB + 3) / 4)                  // 72

#define KV_SCALE_INV  (1.0f / 64.0f)

__device__ __half g_Q[(size_t)NROWS * DOUT];
__device__ __half g_K[(size_t)NROWS * DOUT];
__device__ __half g_V[(size_t)NROWS * DOUT];
__device__ float g_KVpart[(size_t)NB * DOUT * DOUT];
__device__ float g_kspart[(size_t)NB * DOUT];
__device__ float g_sub[4 * (DOUT * DOUT + DOUT)];
__device__ __half g_KVhi[DOUT * DOUT];
__device__ __half g_KVlo[DOUT * DOUT];
__device__ __half g_kshi16[DOUT];
__device__ __half g_kslo16[DOUT];

__device__ __half g_Wh[(size_t)DIN * NQKV];

// ---- qkv smem (BK=32, fused, M=64 CTA) ----
#define A_ROW_B   80
#define A_STAGE_B (MTILE * A_ROW_B)          // 5120
#define BF_ROW_B  784
#define BF_STAGE_B (BK * BF_ROW_B)           // 25088
#define SM_B_OFF  (2 * A_STAGE_B)            // 10240
#define SM_QKV_TOTAL (SM_B_OFF + 2 * BF_STAGE_B)   // 60416 (x2 CTAs = 121 KB)

#define KVT_ROW_B  272
#define KVT_TILE_B (32 * KVT_ROW_B)          // 8704

#define OUT_Q_OFF   0
#define OUT_Q_B     (128 * 272)
#define OUT_HI_OFF  (OUT_Q_OFF + OUT_Q_B)
#define OUT_KV_B    (128 * 272)
#define OUT_LO_OFF  (OUT_HI_OFF + OUT_KV_B)
#define OUT_KS_OFF  (OUT_LO_OFF + OUT_KV_B)
#define OUT_SM_TOTAL (OUT_KS_OFF + 256 * 2)  // 104960

static __device__ __forceinline__ uint32_t smem_u32(const void* p) {
    uint32_t a;
    asm("{ .reg .u64 t; cvta.to.shared.u64 t, %1; cvt.u32.u64 %0, t; }" : "=r"(a) : "l"(p));
    return a;
}
static __device__ __forceinline__ void cp16(uint32_t dst, const void* src) {
    asm volatile("cp.async.cg.shared.global [%0], [%1], 16;" :: "r"(dst), "l"(src) : "memory");
}
static __device__ __forceinline__ void cp16z(uint32_t dst, const void* src, int sz) {
    asm volatile("cp.async.cg.shared.global [%0], [%1], 16, %2;"
                 :: "r"(dst), "l"(src), "r"(sz) : "memory");
}
#define CP_COMMIT()  asm volatile("cp.async.commit_group;" ::: "memory")
#define CP_WAIT(N)   asm volatile("cp.async.wait_group %0;" :: "n"(N) : "memory")

static __device__ __forceinline__ void ldsm_x4(uint32_t* r, uint32_t addr) {
    asm volatile("ldmatrix.sync.aligned.m8n8.x4.shared.b16 {%0,%1,%2,%3}, [%4];"
                 : "=r"(r[0]), "=r"(r[1]), "=r"(r[2]), "=r"(r[3]) : "r"(addr));
}
static __device__ __forceinline__ void ldsm_x4_t(uint32_t* r, uint32_t addr) {
    asm volatile("ldmatrix.sync.aligned.m8n8.x4.trans.shared.b16 {%0,%1,%2,%3}, [%4];"
                 : "=r"(r[0]), "=r"(r[1]), "=r"(r[2]), "=r"(r[3]) : "r"(addr));
}
static __device__ __forceinline__ void mma16816h(float* d, const uint32_t* a,
                                                 const uint32_t* b) {
    asm volatile(
        "mma.sync.aligned.m16n8k16.row.col.f32.f16.f16.f32 "
        "{%0,%1,%2,%3}, {%4,%5,%6,%7}, {%8,%9}, {%0,%1,%2,%3};"
        : "+f"(d[0]), "+f"(d[1]), "+f"(d[2]), "+f"(d[3])
        : "r"(a[0]), "r"(a[1]), "r"(a[2]), "r"(a[3]), "r"(b[0]), "r"(b[1]));
}

__device__ __forceinline__ float elu_p1(float x) {
    return x > 0.0f ? x + 1.0f : expf(x);
}
static __device__ __forceinline__ uint32_t packh2(float a, float b) {
    __half2 p = __floats2half2_rn(a, b);
    return *(uint32_t*)&p;
}

__global__ void noop_kernel() {}

// ============================================================================
// Kernel W: fp16 weight conversion into [k][384].
// ============================================================================
__global__ void convert_w(const float* __restrict__ Wq,
                          const float* __restrict__ Wk,
                          const float* __restrict__ Wv)
{
    int idx = blockIdx.x * 256 + threadIdx.x;
    if (idx >= DIN * NQKV) return;
    int k = idx / NQKV;
    int n = idx % NQKV;
    const float* W = (n < 128) ? Wq : (n < 256) ? Wk : Wv;
    g_Wh[idx] = __float2half_rn(W[(size_t)k * DOUT + (n & 127)]);
}

// ============================================================================
// Kernel A (fused, M=64 CTA): [Q|K|V] = f(h @ [Wq|Wk|Wv]).
// 256 threads, 8 warps (2 wm x 4 wn), warp tile 32x96, BK=32 double-buffered.
// 128 regs x 256 thr = 32K regs -> TWO CTAs co-resident per SM.
// ============================================================================
__global__ __launch_bounds__(256, 2) void qkv_fused(const float* __restrict__ h)
{
    extern __shared__ __align__(256) unsigned char sm[];
    const uint32_t sbase = smem_u32(sm);

    const int row0  = blockIdx.x * MTILE;
    const int tid   = threadIdx.x;
    const int wid   = tid >> 5;
    const int lane  = tid & 31;

    const int wm = wid & 1;
    const int wn = wid >> 1;          // 0..3
    const int m0 = wm * 32;
    const int n0w = wn * 96;

    // A conversion mapping: row = tid>>2 (0..63), seg = (tid&3)*8 floats
    const int arow = tid >> 2;
    const int aseg = (tid & 3) * 8;
    int lrow = row0 + arow;
    if (lrow >= NROWS) lrow = NROWS - 1;
    const float* hrow = h + (size_t)lrow * DIN + aseg;
    const uint32_t a_sts_off = (uint32_t)(arow * A_ROW_B + aseg * 2);

    float acc[2][12][4];
    #pragma unroll
    for (int i = 0; i < 2; i++)
        #pragma unroll
        for (int j = 0; j < 12; j++)
            #pragma unroll
            for (int r = 0; r < 4; r++) acc[i][j][r] = 0.0f;

    const int a_r = (lane & 7) + (lane & 8);
    const int a_c = ((lane >> 4) & 1) * 8;
    const int b_k = (lane & 7) + (lane & 8);
    const int b_n = ((lane >> 4) & 1) * 8;

    auto issue_B = [&](int c, int stage) {
        // 32 rows x 48 c16 = 1536 cp16, 6 per thread
        const size_t src_k0 = (size_t)(c * BK) * NQKV;
        uint32_t dstb = sbase + SM_B_OFF + stage * BF_STAGE_B;
        #pragma unroll
        for (int it = 0; it < 6; it++) {
            int idx = tid + it * 256;
            int r = idx / 48, c16 = idx % 48;
            cp16(dstb + r * BF_ROW_B + c16 * 16,
                 g_Wh + src_k0 + (size_t)r * NQKV + c16 * 8);
        }
        CP_COMMIT();
    };
    auto sts_A = [&](int stage, const float4* v) {
        uint32_t hx[4];
        hx[0] = packh2(v[0].x, v[0].y);
        hx[1] = packh2(v[0].z, v[0].w);
        hx[2] = packh2(v[1].x, v[1].y);
        hx[3] = packh2(v[1].z, v[1].w);
        uint32_t dst = sbase + stage * A_STAGE_B + a_sts_off;
        asm volatile("st.shared.v4.b32 [%0], {%1,%2,%3,%4};" :: "r"(dst),
                     "r"(hx[0]),"r"(hx[1]),"r"(hx[2]),"r"(hx[3]));
    };

    float4 v[2];
    v[0] = *(const float4*)(hrow);
    v[1] = *(const float4*)(hrow + 4);
    issue_B(0, 0);
    sts_A(0, v);

    for (int c = 0; c < NCHUNKS; c++) {
        const int stage = c & 1;

        if (c + 1 < NCHUNKS) {
            v[0] = *(const float4*)(hrow + (c + 1) * BK);
            v[1] = *(const float4*)(hrow + (c + 1) * BK + 4);
        }
        CP_WAIT(0);
        __syncthreads();
        if (c + 1 < NCHUNKS) issue_B(c + 1, stage ^ 1);

        const uint32_t Ab = sbase + stage * A_STAGE_B;
        const uint32_t Bb = sbase + SM_B_OFF + stage * BF_STAGE_B;
        #pragma unroll
        for (int ks = 0; ks < 2; ks++) {
            const int k0 = ks * 16;
            uint32_t afr[2][4];
            #pragma unroll
            for (int im = 0; im < 2; im++)
                ldsm_x4(afr[im], Ab + (uint32_t)((m0 + im * 16 + a_r) * A_ROW_B +
                                                 (k0 + a_c) * 2));
            // process B in two 48-col halves to cap live registers
            #pragma unroll
            for (int hg = 0; hg < 2; hg++) {
                uint32_t bfr[3][4];
                #pragma unroll
                for (int j3 = 0; j3 < 3; j3++)
                    ldsm_x4_t(bfr[j3], Bb + (uint32_t)((k0 + b_k) * BF_ROW_B +
                              (n0w + (hg * 3 + j3) * 16 + b_n) * 2));
                #pragma unroll
                for (int im = 0; im < 2; im++)
                    #pragma unroll
                    for (int j3 = 0; j3 < 3; j3++) {
                        const int j = (hg * 3 + j3) * 2;
                        mma16816h(acc[im][j + 0], afr[im], &bfr[j3][0]);
                        mma16816h(acc[im][j + 1], afr[im], &bfr[j3][2]);
                    }
            }
        }

        if (c + 1 < NCHUNKS) sts_A(stage ^ 1, v);
    }

    // ---- epilogue ----
    const int g = lane >> 2;
    const int t = lane & 3;

    #pragma unroll
    for (int im = 0; im < 2; im++) {
        const int r0 = row0 + m0 + im * 16 + g;
        const int r1 = r0 + 8;
        #pragma unroll
        for (int j = 0; j < 12; j++) {
            const int col = n0w + j * 8 + t * 2;
            const int which = col >> 7;
            const int lc = col & 127;
            __half* Out = (which == 0) ? g_Q : (which == 1) ? g_K : g_V;
            const bool act = (which < 2);
            float c0 = acc[im][j][0], c1 = acc[im][j][1];
            float c2 = acc[im][j][2], c3 = acc[im][j][3];
            if (act) {
                c0 = elu_p1(c0); c1 = elu_p1(c1);
                c2 = elu_p1(c2); c3 = elu_p1(c3);
            }
            if (r0 < NROWS)
                *(__half2*)(Out + (size_t)r0 * DOUT + lc) = __floats2half2_rn(c0, c1);
            if (r1 < NROWS)
                *(__half2*)(Out + (size_t)r1 * DOUT + lc) = __floats2half2_rn(c2, c3);
        }
    }
}

// ============================================================================
// Kernel B: partial KV = K_chunk^T @ V_chunk via fp16 mma + k_sum via MMA.
// ============================================================================
__global__ __launch_bounds__(256, 2) void kv_mma()
{
    __shared__ __align__(16) unsigned char sm[2 * 2 * KVT_TILE_B];
    const uint32_t sb = smem_u32(sm);

    const int tid  = threadIdx.x;
    const int wid  = tid >> 5;
    const int lane = tid & 31;
    const int m0 = (wid & 3) * 32;
    const int n0 = (wid >> 2) * 64;
    const int wn = wid >> 2;
    const int base = blockIdx.x * CHUNK;

    float acc[2][8][4];
    #pragma unroll
    for (int i = 0; i < 2; i++)
        #pragma unroll
        for (int j = 0; j < 8; j++)
            #pragma unroll
            for (int r = 0; r < 4; r++) acc[i][j][r] = 0.0f;
    float acc_ks[2][4];
    #pragma unroll
    for (int i = 0; i < 2; i++)
        #pragma unroll
        for (int r = 0; r < 4; r++) acc_ks[i][r] = 0.0f;

    const uint32_t b_ones[2] = {0x3C003C00u, 0x3C003C00u};

    auto issue = [&](int it, int stage) {
        #pragma unroll
        for (int q = 0; q < 4; q++) {
            int idx  = tid + q * 256;
            int tile = idx >> 9;
            int row  = (idx >> 4) & 31;
            int c16  = idx & 15;
            int grow = base + it * 32 + row;
            const __half* src = (tile ? g_V : g_K) + (size_t)grow * DOUT + c16 * 8;
            uint32_t dst = sb + stage * 2 * KVT_TILE_B + tile * KVT_TILE_B +
                           row * KVT_ROW_B + c16 * 16;
            cp16z(dst, src, (grow < NROWS) ? 16 : 0);
        }
        CP_COMMIT();
    };

    const int trow = (lane & 7) + (lane & 8);
    const int tcol = ((lane >> 4) & 1) * 8;

    issue(0, 0);

    for (int it = 0; it < SLABS; it++) {
        const int stage = it & 1;
        CP_WAIT(0);
        __syncthreads();
        if (it + 1 < SLABS) issue(it + 1, stage ^ 1);

        const uint32_t Kb = sb + stage * 2 * KVT_TILE_B;
        const uint32_t Vb = Kb + KVT_TILE_B;

        #pragma unroll
        for (int ks = 0; ks < 2; ks++) {
            const int k0 = ks * 16;
            uint32_t afr[2][4];
            #pragma unroll
            for (int im = 0; im < 2; im++) {
                uint32_t t4[4];
                ldsm_x4_t(t4, Kb + (uint32_t)((k0 + trow) * KVT_ROW_B +
                                              (m0 + im * 16 + tcol) * 2));
                afr[im][0] = t4[0]; afr[im][1] = t4[2];
                afr[im][2] = t4[1]; afr[im][3] = t4[3];
            }
            uint32_t bfr[4][4];
            #pragma unroll
            for (int jn = 0; jn < 4; jn++)
                ldsm_x4_t(bfr[jn], Vb + (uint32_t)((k0 + trow) * KVT_ROW_B +
                                                   (n0 + jn * 16 + tcol) * 2));
            #pragma unroll
            for (int im = 0; im < 2; im++)
                #pragma unroll
                for (int jn = 0; jn < 4; jn++) {
                    mma16816h(acc[im][jn * 2 + 0], afr[im], &bfr[jn][0]);
                    mma16816h(acc[im][jn * 2 + 1], afr[im], &bfr[jn][2]);
                }
            if (wn == 0) {
                mma16816h(acc_ks[0], afr[0], b_ones);
                mma16816h(acc_ks[1], afr[1], b_ones);
            }
        }
    }

    float* kvout = g_KVpart + (size_t)blockIdx.x * (DOUT * DOUT);
    const int g = lane >> 2;
    const int t = lane & 3;
    #pragma unroll
    for (int im = 0; im < 2; im++) {
        const int r0 = m0 + im * 16 + g;
        #pragma unroll
        for (int j = 0; j < 8; j++) {
            const int col = n0 + j * 8 + t * 2;
            *(float2*)(kvout + (size_t)r0 * DOUT + col) =
                make_float2(acc[im][j][0], acc[im][j][1]);
            *(float2*)(kvout + (size_t)(r0 + 8) * DOUT + col) =
                make_float2(acc[im][j][2], acc[im][j][3]);
        }
    }
    if (wn == 0 && t == 0) {
        #pragma unroll
        for (int im = 0; im < 2; im++) {
            const int r = m0 + im * 16 + g;
            g_kspart[(size_t)blockIdx.x * DOUT + r]     = acc_ks[im][0];
            g_kspart[(size_t)blockIdx.x * DOUT + r + 8] = acc_ks[im][2];
        }
    }
}

// ============================================================================
// Reduce phase 1: 4 sub-range partial sums. Grid (65, 4).
// ============================================================================
__global__ void reduce1()
{
    const int sub = blockIdx.y;
    const int i = blockIdx.x * blockDim.x + threadIdx.x;
    if (i >= DOUT * DOUT + DOUT) return;
    const int b0 = sub * NB4;
    const int b1 = (b0 + NB4 < NB) ? b0 + NB4 : NB;

    float s0 = 0.0f, s1 = 0.0f, s2 = 0.0f, s3 = 0.0f;
    if (i < DOUT * DOUT) {
        int b = b0;
        for (; b + 3 < b1; b += 4) {
            s0 += g_KVpart[(size_t)(b + 0) * (DOUT * DOUT) + i];
            s1 += g_KVpart[(size_t)(b + 1) * (DOUT * DOUT) + i];
            s2 += g_KVpart[(size_t)(b + 2) * (DOUT * DOUT) + i];
            s3 += g_KVpart[(size_t)(b + 3) * (DOUT * DOUT) + i];
        }
        for (; b < b1; b++) s0 += g_KVpart[(size_t)b * (DOUT * DOUT) + i];
    } else {
        const int j = i - DOUT * DOUT;
        int b = b0;
        for (; b + 3 < b1; b += 4) {
            s0 += g_kspart[(size_t)(b + 0) * DOUT + j];
            s1 += g_kspart[(size_t)(b + 1) * DOUT + j];
            s2 += g_kspart[(size_t)(b + 2) * DOUT + j];
            s3 += g_kspart[(size_t)(b + 3) * DOUT + j];
        }
        for (; b < b1; b++) s0 += g_kspart[(size_t)b * DOUT + j];
    }
    g_sub[sub * (DOUT * DOUT + DOUT) + i] = ((s0 + s1) + (s2 + s3));
}

// ============================================================================
// Reduce phase 2: combine 4 subs, emit fp16 hi/lo KV and ksum.
// ============================================================================
__global__ void reduce2()
{
    const int i = blockIdx.x * blockDim.x + threadIdx.x;
    if (i >= DOUT * DOUT + DOUT) return;
    const int stride = DOUT * DOUT + DOUT;
    float s = (g_sub[i] + g_sub[stride + i]) +
              (g_sub[2 * stride + i] + g_sub[3 * stride + i]);
    if (i < DOUT * DOUT) {
        s *= KV_SCALE_INV;
        __half hi = __float2half_rn(s);
        g_KVhi[i] = hi;
        g_KVlo[i] = __float2half_rn(s - __half2float(hi));
    } else {
        const int j = i - DOUT * DOUT;
        s *= 0.125f;
        __half hi = __float2half_rn(s);
        g_kshi16[j] = hi;
        g_kslo16[j] = __float2half_rn(s - __half2float(hi));
    }
}

// ============================================================================
// Kernel C: out = elu((Q @ KV) / (Q @ ksum)) via fp16 mma. 128-row blocks.
// ============================================================================
__global__ __launch_bounds__(512, 1) void out_mma(float* __restrict__ out)
{
    extern __shared__ __align__(256) unsigned char smo[];
    const uint32_t sb = smem_u32(smo);

    const int tid  = threadIdx.x;
    const int wid  = tid >> 5;
    const int lane = tid & 31;
    const int row0 = blockIdx.x * 128;

    const int m0 = (wid & 3) * 32;
    const int n0 = (wid >> 2) * 32;

    #pragma unroll
    for (int q = 0; q < 4; q++) {
        int idx = tid + q * 512;
        int r = idx >> 4, c16 = idx & 15;
        int grow = row0 + r;
        cp16z(sb + OUT_Q_OFF + r * 272 + c16 * 16,
              g_Q + (size_t)grow * DOUT + c16 * 8,
              (grow < NROWS) ? 16 : 0);
    }
    #pragma unroll
    for (int q = 0; q < 8; q++) {
        int idx = tid + q * 512;
        int part = idx >> 11;
        int rem = idx & 2047;
        int r = rem >> 4, c16 = rem & 15;
        const __half* src = (part ? g_KVlo : g_KVhi) + r * DOUT + c16 * 8;
        cp16(sb + (part ? OUT_LO_OFF : OUT_HI_OFF) + r * 272 + c16 * 16, src);
    }
    CP_COMMIT();
    __half* kss = (__half*)(smo + OUT_KS_OFF);
    if (tid < 128) kss[tid] = g_kshi16[tid];
    else if (tid < 256) kss[tid] = g_kslo16[tid - 128];
    CP_WAIT(0);
    __syncthreads();

    float acc[2][4][4];
    #pragma unroll
    for (int i = 0; i < 2; i++)
        #pragma unroll
        for (int j = 0; j < 4; j++)
            #pragma unroll
            for (int r = 0; r < 4; r++) acc[i][j][r] = 0.0f;
    float acc_z[2][4];
    #pragma unroll
    for (int i = 0; i < 2; i++)
        #pragma unroll
        for (int r = 0; r < 4; r++) acc_z[i][r] = 0.0f;

    const int a_r = (lane & 7) + (lane & 8);
    const int a_c = ((lane >> 4) & 1) * 8;
    const int zcol = lane >> 2;
    const int zk   = (lane & 3) * 2;

    #pragma unroll
    for (int ks = 0; ks < 8; ks++) {
        const int k0 = ks * 16;
        uint32_t afr[2][4];
        #pragma unroll
        for (int im = 0; im < 2; im++)
            ldsm_x4(afr[im], sb + OUT_Q_OFF +
                    (uint32_t)((m0 + im * 16 + a_r) * 272 + (k0 + a_c) * 2));
        #pragma unroll
        for (int part = 0; part < 2; part++) {
            const uint32_t Bb = sb + (part ? OUT_LO_OFF : OUT_HI_OFF);
            uint32_t bfr[2][4];
            #pragma unroll
            for (int jn = 0; jn < 2; jn++)
                ldsm_x4_t(bfr[jn], Bb + (uint32_t)((k0 + a_r) * 272 +
                                                   (n0 + jn * 16 + a_c) * 2));
            #pragma unroll
            for (int im = 0; im < 2; im++)
                #pragma unroll
                for (int jn = 0; jn < 2; jn++) {
                    mma16816h(acc[im][jn * 2 + 0], afr[im], &bfr[jn][0]);
                    mma16816h(acc[im][jn * 2 + 1], afr[im], &bfr[jn][2]);
                }
        }
        uint32_t zb[2] = {0u, 0u};
        if (zcol < 2) {
            const __half* kp = kss + zcol * 128 + k0 + zk;
            zb[0] = *(const uint32_t*)(kp);
            zb[1] = *(const uint32_t*)(kp + 8);
        }
        mma16816h(acc_z[0], afr[0], zb);
        mma16816h(acc_z[1], afr[1], zb);
    }

    const int g = lane >> 2;
    const int t = lane & 3;
    #pragma unroll
    for (int im = 0; im < 2; im++) {
        float den0 = acc_z[im][0] + acc_z[im][1];
        float den1 = acc_z[im][2] + acc_z[im][3];
        den0 = __shfl_sync(0xffffffffu, den0, lane & 28);
        den1 = __shfl_sync(0xffffffffu, den1, lane & 28);
        const float z0 = 8.0f / den0;
        const float z1 = 8.0f / den1;
        const int gr0 = row0 + m0 + im * 16 + g;
        const int gr1 = gr0 + 8;
        #pragma unroll
        for (int j = 0; j < 4; j++) {
            const int col = n0 + j * 8 + t * 2;
            float x0 = acc[im][j][0] * z0;
            float x1 = acc[im][j][1] * z0;
            float x2 = acc[im][j][2] * z1;
            float x3 = acc[im][j][3] * z1;
            x0 = x0 > 0.0f ? x0 : expm1f(x0);
            x1 = x1 > 0.0f ? x1 : expm1f(x1);
            x2 = x2 > 0.0f ? x2 : expm1f(x2);
            x3 = x3 > 0.0f ? x3 : expm1f(x3);
            if (gr0 < NROWS)
                *(float2*)(out + (size_t)gr0 * DOUT + col) = make_float2(x0, x1);
            if (gr1 < NROWS)
                *(float2*)(out + (size_t)gr1 * DOUT + col) = make_float2(x2, x3);
        }
    }
}

// ============================================================================
// Launch
// ============================================================================
extern "C" void kernel_launch(void* const* d_in, const int* in_sizes, int n_in,
                              void* d_out, int out_size)
{
    const float* h  = (const float*)d_in[0];
    const float* Wq = (const float*)d_in[1];
    const float* Wk = (const float*)d_in[2];
    const float* Wv = (const float*)d_in[3];
    float* out = (float*)d_out;

    cudaFuncSetAttribute(qkv_fused, cudaFuncAttributeMaxDynamicSharedMemorySize, SM_QKV_TOTAL);
    cudaFuncSetAttribute(out_mma, cudaFuncAttributeMaxDynamicSharedMemorySize, OUT_SM_TOTAL);

    convert_w<<<(DIN * NQKV + 255) / 256, 256>>>(Wq, Wk, Wv);   // idx 0
    noop_kernel<<<1, 32>>>();                                    // idx 1
    noop_kernel<<<1, 32>>>();                                    // idx 2

    qkv_fused<<<NBLK_M, 256, SM_QKV_TOTAL>>>(h);                 // idx 3 (profiled)

    kv_mma<<<NB, 256>>>();

    dim3 gridR1((DOUT * DOUT + DOUT + 255) / 256, 4);
    reduce1<<<gridR1, 256>>>();
    reduce2<<<(DOUT * DOUT + DOUT + 255) / 256, 256>>>();

    out_mma<<<(NROWS + 127) / 128, 512, OUT_SM_TOTAL>>>(out);
}

// round 15
// speedup vs baseline: 1.3282x; 1.0626x over previous
#include <cuda_runtime.h>
#include <cuda_fp16.h>
#include <math.h>
#include <stdint.h>

#define NROWS 200000
#define DIN   512
#define DOUT  128
#define NQKV  384
#define BK    32
#define NCHUNKS (DIN / BK)                    // 16
#define MTILE 128
#define NBLK_M ((NROWS + MTILE - 1) / MTILE)  // 1563

#define CHUNK 704
#define SLABS (CHUNK / 32)                    // 22
#define NB    ((NROWS + CHUNK - 1) / CHUNK)   // 285
#define NB4   ((NB + 3) / 4)                  // 72

#define KV_SCALE_INV  (1.0f / 64.0f)

__device__ __half g_Q[(size_t)NROWS * DOUT];
__device__ __half g_K[(size_t)NROWS * DOUT];
__device__ __half g_V[(size_t)NROWS * DOUT];
__device__ float g_KVpart[(size_t)NB * DOUT * DOUT];
__device__ float g_kspart[(size_t)NB * DOUT];
__device__ float g_sub[4 * (DOUT * DOUT + DOUT)];
__device__ __half g_KVhi[DOUT * DOUT];
__device__ __half g_KVlo[DOUT * DOUT];
__device__ __half g_kshi16[DOUT];
__device__ __half g_kslo16[DOUT];

__device__ __half g_Wh[(size_t)DIN * NQKV];

// ---- qkv smem (BK=32, fused, M=128 CTA — best measured config) ----
#define A_ROW_B   80
#define A_STAGE_B (MTILE * A_ROW_B)          // 10240
#define BF_ROW_B  784
#define BF_STAGE_B (BK * BF_ROW_B)           // 25088
#define SM_B_OFF  (2 * A_STAGE_B)            // 20480
#define SM_QKV_TOTAL (SM_B_OFF + 2 * BF_STAGE_B)   // 70656

#define KVT_ROW_B  272
#define KVT_TILE_B (32 * KVT_ROW_B)          // 8704

#define OUT_Q_OFF   0
#define OUT_Q_B     (128 * 272)
#define OUT_HI_OFF  (OUT_Q_OFF + OUT_Q_B)
#define OUT_KV_B    (128 * 272)
#define OUT_LO_OFF  (OUT_HI_OFF + OUT_KV_B)
#define OUT_KS_OFF  (OUT_LO_OFF + OUT_KV_B)
#define OUT_SM_TOTAL (OUT_KS_OFF + 256 * 2)  // 104960

static __device__ __forceinline__ uint32_t smem_u32(const void* p) {
    uint32_t a;
    asm("{ .reg .u64 t; cvta.to.shared.u64 t, %1; cvt.u32.u64 %0, t; }" : "=r"(a) : "l"(p));
    return a;
}
static __device__ __forceinline__ void cp16(uint32_t dst, const void* src) {
    asm volatile("cp.async.cg.shared.global [%0], [%1], 16;" :: "r"(dst), "l"(src) : "memory");
}
static __device__ __forceinline__ void cp16z(uint32_t dst, const void* src, int sz) {
    asm volatile("cp.async.cg.shared.global [%0], [%1], 16, %2;"
                 :: "r"(dst), "l"(src), "r"(sz) : "memory");
}
#define CP_COMMIT()  asm volatile("cp.async.commit_group;" ::: "memory")
#define CP_WAIT(N)   asm volatile("cp.async.wait_group %0;" :: "n"(N) : "memory")

static __device__ __forceinline__ void ldsm_x4(uint32_t* r, uint32_t addr) {
    asm volatile("ldmatrix.sync.aligned.m8n8.x4.shared.b16 {%0,%1,%2,%3}, [%4];"
                 : "=r"(r[0]), "=r"(r[1]), "=r"(r[2]), "=r"(r[3]) : "r"(addr));
}
static __device__ __forceinline__ void ldsm_x4_t(uint32_t* r, uint32_t addr) {
    asm volatile("ldmatrix.sync.aligned.m8n8.x4.trans.shared.b16 {%0,%1,%2,%3}, [%4];"
                 : "=r"(r[0]), "=r"(r[1]), "=r"(r[2]), "=r"(r[3]) : "r"(addr));
}
static __device__ __forceinline__ void mma16816h(float* d, const uint32_t* a,
                                                 const uint32_t* b) {
    asm volatile(
        "mma.sync.aligned.m16n8k16.row.col.f32.f16.f16.f32 "
        "{%0,%1,%2,%3}, {%4,%5,%6,%7}, {%8,%9}, {%0,%1,%2,%3};"
        : "+f"(d[0]), "+f"(d[1]), "+f"(d[2]), "+f"(d[3])
        : "r"(a[0]), "r"(a[1]), "r"(a[2]), "r"(a[3]), "r"(b[0]), "r"(b[1]));
}

__device__ __forceinline__ float elu_p1(float x) {
    return x > 0.0f ? x + 1.0f : expf(x);
}
static __device__ __forceinline__ uint32_t packh2(float a, float b) {
    __half2 p = __floats2half2_rn(a, b);
    return *(uint32_t*)&p;
}

// ============================================================================
// Kernel W: fp16 weight conversion into [k][384].
// ============================================================================
__global__ void convert_w(const float* __restrict__ Wq,
                          const float* __restrict__ Wk,
                          const float* __restrict__ Wv)
{
    int idx = blockIdx.x * 256 + threadIdx.x;
    if (idx >= DIN * NQKV) return;
    int k = idx / NQKV;
    int n = idx % NQKV;
    const float* W = (n < 128) ? Wq : (n < 256) ? Wk : Wv;
    g_Wh[idx] = __float2half_rn(W[(size_t)k * DOUT + (n & 127)]);
}

// ============================================================================
// Kernel A (fused): [Q|K|V] = f(h @ [Wq|Wk|Wv]) in ONE CTA per m-tile.
// 512 threads, 16 warps (4 wm x 4 wn), warp tile 32x96, N=384, BK=32.
// Best measured configuration (R11: 333.7 us).
// ============================================================================
__global__ __launch_bounds__(512, 1) void qkv_fused(const float* __restrict__ h)
{
    extern __shared__ __align__(256) unsigned char sm[];
    const uint32_t sbase = smem_u32(sm);

    const int row0  = blockIdx.x * MTILE;
    const int tid   = threadIdx.x;
    const int wid   = tid >> 5;
    const int lane  = tid & 31;

    const int wm = wid & 3;
    const int wn = wid >> 2;
    const int m0 = wm * 32;
    const int n0w = wn * 96;

    const int arow = tid >> 2;
    const int aseg = (tid & 3) * 8;
    int lrow = row0 + arow;
    if (lrow >= NROWS) lrow = NROWS - 1;
    const float* hrow = h + (size_t)lrow * DIN + aseg;
    const uint32_t a_sts_off = (uint32_t)(arow * A_ROW_B + aseg * 2);

    float acc[2][12][4];
    #pragma unroll
    for (int i = 0; i < 2; i++)
        #pragma unroll
        for (int j = 0; j < 12; j++)
            #pragma unroll
            for (int r = 0; r < 4; r++) acc[i][j][r] = 0.0f;

    const int a_r = (lane & 7) + (lane & 8);
    const int a_c = ((lane >> 4) & 1) * 8;
    const int b_k = (lane & 7) + (lane & 8);
    const int b_n = ((lane >> 4) & 1) * 8;

    auto issue_B = [&](int c, int stage) {
        const size_t src_k0 = (size_t)(c * BK) * NQKV;
        uint32_t dstb = sbase + SM_B_OFF + stage * BF_STAGE_B;
        #pragma unroll
        for (int it = 0; it < 3; it++) {
            int idx = tid + it * 512;
            int r = idx / 48, c16 = idx % 48;
            cp16(dstb + r * BF_ROW_B + c16 * 16,
                 g_Wh + src_k0 + (size_t)r * NQKV + c16 * 8);
        }
        CP_COMMIT();
    };
    auto sts_A = [&](int stage, const float4* v) {
        uint32_t hx[4];
        hx[0] = packh2(v[0].x, v[0].y);
        hx[1] = packh2(v[0].z, v[0].w);
        hx[2] = packh2(v[1].x, v[1].y);
        hx[3] = packh2(v[1].z, v[1].w);
        uint32_t dst = sbase + stage * A_STAGE_B + a_sts_off;
        asm volatile("st.shared.v4.b32 [%0], {%1,%2,%3,%4};" :: "r"(dst),
                     "r"(hx[0]),"r"(hx[1]),"r"(hx[2]),"r"(hx[3]));
    };

    float4 v[2];
    v[0] = *(const float4*)(hrow);
    v[1] = *(const float4*)(hrow + 4);
    issue_B(0, 0);
    sts_A(0, v);

    for (int c = 0; c < NCHUNKS; c++) {
        const int stage = c & 1;

        if (c + 1 < NCHUNKS) {
            v[0] = *(const float4*)(hrow + (c + 1) * BK);
            v[1] = *(const float4*)(hrow + (c + 1) * BK + 4);
        }
        CP_WAIT(0);
        __syncthreads();
        if (c + 1 < NCHUNKS) issue_B(c + 1, stage ^ 1);

        const uint32_t Ab = sbase + stage * A_STAGE_B;
        const uint32_t Bb = sbase + SM_B_OFF + stage * BF_STAGE_B;
        #pragma unroll
        for (int ks = 0; ks < 2; ks++) {
            const int k0 = ks * 16;
            uint32_t afr[2][4];
            #pragma unroll
            for (int im = 0; im < 2; im++)
                ldsm_x4(afr[im], Ab + (uint32_t)((m0 + im * 16 + a_r) * A_ROW_B +
                                                 (k0 + a_c) * 2));
            #pragma unroll
            for (int hg = 0; hg < 2; hg++) {
                uint32_t bfr[3][4];
                #pragma unroll
                for (int j3 = 0; j3 < 3; j3++)
                    ldsm_x4_t(bfr[j3], Bb + (uint32_t)((k0 + b_k) * BF_ROW_B +
                              (n0w + (hg * 3 + j3) * 16 + b_n) * 2));
                #pragma unroll
                for (int im = 0; im < 2; im++)
                    #pragma unroll
                    for (int j3 = 0; j3 < 3; j3++) {
                        const int j = (hg * 3 + j3) * 2;
                        mma16816h(acc[im][j + 0], afr[im], &bfr[j3][0]);
                        mma16816h(acc[im][j + 1], afr[im], &bfr[j3][2]);
                    }
            }
        }

        if (c + 1 < NCHUNKS) sts_A(stage ^ 1, v);
    }

    const int g = lane >> 2;
    const int t = lane & 3;

    #pragma unroll
    for (int im = 0; im < 2; im++) {
        const int r0 = row0 + m0 + im * 16 + g;
        const int r1 = r0 + 8;
        #pragma unroll
        for (int j = 0; j < 12; j++) {
            const int col = n0w + j * 8 + t * 2;
            const int which = col >> 7;
            const int lc = col & 127;
            __half* Out = (which == 0) ? g_Q : (which == 1) ? g_K : g_V;
            const bool act = (which < 2);
            float c0 = acc[im][j][0], c1 = acc[im][j][1];
            float c2 = acc[im][j][2], c3 = acc[im][j][3];
            if (act) {
                c0 = elu_p1(c0); c1 = elu_p1(c1);
                c2 = elu_p1(c2); c3 = elu_p1(c3);
            }
            if (r0 < NROWS)
                *(__half2*)(Out + (size_t)r0 * DOUT + lc) = __floats2half2_rn(c0, c1);
            if (r1 < NROWS)
                *(__half2*)(Out + (size_t)r1 * DOUT + lc) = __floats2half2_rn(c2, c3);
        }
    }
}

// ============================================================================
// Kernel B: partial KV = K_chunk^T @ V_chunk via fp16 mma + k_sum via MMA.
// CHUNK=704 -> 285 blocks: single wave at occ 2.
// ============================================================================
__global__ __launch_bounds__(256, 2) void kv_mma()
{
    __shared__ __align__(16) unsigned char sm[2 * 2 * KVT_TILE_B];
    const uint32_t sb = smem_u32(sm);

    const int tid  = threadIdx.x;
    const int wid  = tid >> 5;
    const int lane = tid & 31;
    const int m0 = (wid & 3) * 32;
    const int n0 = (wid >> 2) * 64;
    const int wn = wid >> 2;
    const int base = blockIdx.x * CHUNK;

    float acc[2][8][4];
    #pragma unroll
    for (int i = 0; i < 2; i++)
        #pragma unroll
        for (int j = 0; j < 8; j++)
            #pragma unroll
            for (int r = 0; r < 4; r++) acc[i][j][r] = 0.0f;
    float acc_ks[2][4];
    #pragma unroll
    for (int i = 0; i < 2; i++)
        #pragma unroll
        for (int r = 0; r < 4; r++) acc_ks[i][r] = 0.0f;

    const uint32_t b_ones[2] = {0x3C003C00u, 0x3C003C00u};

    auto issue = [&](int it, int stage) {
        #pragma unroll
        for (int q = 0; q < 4; q++) {
            int idx  = tid + q * 256;
            int tile = idx >> 9;
            int row  = (idx >> 4) & 31;
            int c16  = idx & 15;
            int grow = base + it * 32 + row;
            const __half* src = (tile ? g_V : g_K) + (size_t)grow * DOUT + c16 * 8;
            uint32_t dst = sb + stage * 2 * KVT_TILE_B + tile * KVT_TILE_B +
                           row * KVT_ROW_B + c16 * 16;
            cp16z(dst, src, (grow < NROWS) ? 16 : 0);
        }
        CP_COMMIT();
    };

    const int trow = (lane & 7) + (lane & 8);
    const int tcol = ((lane >> 4) & 1) * 8;

    issue(0, 0);

    for (int it = 0; it < SLABS; it++) {
        const int stage = it & 1;
        CP_WAIT(0);
        __syncthreads();
        if (it + 1 < SLABS) issue(it + 1, stage ^ 1);

        const uint32_t Kb = sb + stage * 2 * KVT_TILE_B;
        const uint32_t Vb = Kb + KVT_TILE_B;

        #pragma unroll
        for (int ks = 0; ks < 2; ks++) {
            const int k0 = ks * 16;
            uint32_t afr[2][4];
            #pragma unroll
            for (int im = 0; im < 2; im++) {
                uint32_t t4[4];
                ldsm_x4_t(t4, Kb + (uint32_t)((k0 + trow) * KVT_ROW_B +
                                              (m0 + im * 16 + tcol) * 2));
                afr[im][0] = t4[0]; afr[im][1] = t4[2];
                afr[im][2] = t4[1]; afr[im][3] = t4[3];
            }
            uint32_t bfr[4][4];
            #pragma unroll
            for (int jn = 0; jn < 4; jn++)
                ldsm_x4_t(bfr[jn], Vb + (uint32_t)((k0 + trow) * KVT_ROW_B +
                                                   (n0 + jn * 16 + tcol) * 2));
            #pragma unroll
            for (int im = 0; im < 2; im++)
                #pragma unroll
                for (int jn = 0; jn < 4; jn++) {
                    mma16816h(acc[im][jn * 2 + 0], afr[im], &bfr[jn][0]);
                    mma16816h(acc[im][jn * 2 + 1], afr[im], &bfr[jn][2]);
                }
            if (wn == 0) {
                mma16816h(acc_ks[0], afr[0], b_ones);
                mma16816h(acc_ks[1], afr[1], b_ones);
            }
        }
    }

    float* kvout = g_KVpart + (size_t)blockIdx.x * (DOUT * DOUT);
    const int g = lane >> 2;
    const int t = lane & 3;
    #pragma unroll
    for (int im = 0; im < 2; im++) {
        const int r0 = m0 + im * 16 + g;
        #pragma unroll
        for (int j = 0; j < 8; j++) {
            const int col = n0 + j * 8 + t * 2;
            *(float2*)(kvout + (size_t)r0 * DOUT + col) =
                make_float2(acc[im][j][0], acc[im][j][1]);
            *(float2*)(kvout + (size_t)(r0 + 8) * DOUT + col) =
                make_float2(acc[im][j][2], acc[im][j][3]);
        }
    }
    if (wn == 0 && t == 0) {
        #pragma unroll
        for (int im = 0; im < 2; im++) {
            const int r = m0 + im * 16 + g;
            g_kspart[(size_t)blockIdx.x * DOUT + r]     = acc_ks[im][0];
            g_kspart[(size_t)blockIdx.x * DOUT + r + 8] = acc_ks[im][2];
        }
    }
}

// ============================================================================
// Reduce phase 1: 4 sub-range partial sums. Grid (65, 4).
// ============================================================================
__global__ void reduce1()
{
    const int sub = blockIdx.y;
    const int i = blockIdx.x * blockDim.x + threadIdx.x;
    if (i >= DOUT * DOUT + DOUT) return;
    const int b0 = sub * NB4;
    const int b1 = (b0 + NB4 < NB) ? b0 + NB4 : NB;

    float s0 = 0.0f, s1 = 0.0f, s2 = 0.0f, s3 = 0.0f;
    if (i < DOUT * DOUT) {
        int b = b0;
        for (; b + 3 < b1; b += 4) {
            s0 += g_KVpart[(size_t)(b + 0) * (DOUT * DOUT) + i];
            s1 += g_KVpart[(size_t)(b + 1) * (DOUT * DOUT) + i];
            s2 += g_KVpart[(size_t)(b + 2) * (DOUT * DOUT) + i];
            s3 += g_KVpart[(size_t)(b + 3) * (DOUT * DOUT) + i];
        }
        for (; b < b1; b++) s0 += g_KVpart[(size_t)b * (DOUT * DOUT) + i];
    } else {
        const int j = i - DOUT * DOUT;
        int b = b0;
        for (; b + 3 < b1; b += 4) {
            s0 += g_kspart[(size_t)(b + 0) * DOUT + j];
            s1 += g_kspart[(size_t)(b + 1) * DOUT + j];
            s2 += g_kspart[(size_t)(b + 2) * DOUT + j];
            s3 += g_kspart[(size_t)(b + 3) * DOUT + j];
        }
        for (; b < b1; b++) s0 += g_kspart[(size_t)b * DOUT + j];
    }
    g_sub[sub * (DOUT * DOUT + DOUT) + i] = ((s0 + s1) + (s2 + s3));
}

// ============================================================================
// Reduce phase 2: combine 4 subs, emit fp16 hi/lo KV and ksum.
// ============================================================================
__global__ void reduce2()
{
    const int i = blockIdx.x * blockDim.x + threadIdx.x;
    if (i >= DOUT * DOUT + DOUT) return;
    const int stride = DOUT * DOUT + DOUT;
    float s = (g_sub[i] + g_sub[stride + i]) +
              (g_sub[2 * stride + i] + g_sub[3 * stride + i]);
    if (i < DOUT * DOUT) {
        s *= KV_SCALE_INV;
        __half hi = __float2half_rn(s);
        g_KVhi[i] = hi;
        g_KVlo[i] = __float2half_rn(s - __half2float(hi));
    } else {
        const int j = i - DOUT * DOUT;
        s *= 0.125f;
        __half hi = __float2half_rn(s);
        g_kshi16[j] = hi;
        g_kslo16[j] = __float2half_rn(s - __half2float(hi));
    }
}

// ============================================================================
// Kernel C: out = elu((Q @ KV) / (Q @ ksum)) via fp16 mma. 128-row blocks.
// ============================================================================
__global__ __launch_bounds__(512, 1) void out_mma(float* __restrict__ out)
{
    extern __shared__ __align__(256) unsigned char smo[];
    const uint32_t sb = smem_u32(smo);

    const int tid  = threadIdx.x;
    const int wid  = tid >> 5;
    const int lane = tid & 31;
    const int row0 = blockIdx.x * 128;

    const int m0 = (wid & 3) * 32;
    const int n0 = (wid >> 2) * 32;

    #pragma unroll
    for (int q = 0; q < 4; q++) {
        int idx = tid + q * 512;
        int r = idx >> 4, c16 = idx & 15;
        int grow = row0 + r;
        cp16z(sb + OUT_Q_OFF + r * 272 + c16 * 16,
              g_Q + (size_t)grow * DOUT + c16 * 8,
              (grow < NROWS) ? 16 : 0);
    }
    #pragma unroll
    for (int q = 0; q < 8; q++) {
        int idx = tid + q * 512;
        int part = idx >> 11;
        int rem = idx & 2047;
        int r = rem >> 4, c16 = rem & 15;
        const __half* src = (part ? g_KVlo : g_KVhi) + r * DOUT + c16 * 8;
        cp16(sb + (part ? OUT_LO_OFF : OUT_HI_OFF) + r * 272 + c16 * 16, src);
    }
    CP_COMMIT();
    __half* kss = (__half*)(smo + OUT_KS_OFF);
    if (tid < 128) kss[tid] = g_kshi16[tid];
    else if (tid < 256) kss[tid] = g_kslo16[tid - 128];
    CP_WAIT(0);
    __syncthreads();

    float acc[2][4][4];
    #pragma unroll
    for (int i = 0; i < 2; i++)
        #pragma unroll
        for (int j = 0; j < 4; j++)
            #pragma unroll
            for (int r = 0; r < 4; r++) acc[i][j][r] = 0.0f;
    float acc_z[2][4];
    #pragma unroll
    for (int i = 0; i < 2; i++)
        #pragma unroll
        for (int r = 0; r < 4; r++) acc_z[i][r] = 0.0f;

    const int a_r = (lane & 7) + (lane & 8);
    const int a_c = ((lane >> 4) & 1) * 8;
    const int zcol = lane >> 2;
    const int zk   = (lane & 3) * 2;

    #pragma unroll
    for (int ks = 0; ks < 8; ks++) {
        const int k0 = ks * 16;
        uint32_t afr[2][4];
        #pragma unroll
        for (int im = 0; im < 2; im++)
            ldsm_x4(afr[im], sb + OUT_Q_OFF +
                    (uint32_t)((m0 + im * 16 + a_r) * 272 + (k0 + a_c) * 2));
        #pragma unroll
        for (int part = 0; part < 2; part++) {
            const uint32_t Bb = sb + (part ? OUT_LO_OFF : OUT_HI_OFF);
            uint32_t bfr[2][4];
            #pragma unroll
            for (int jn = 0; jn < 2; jn++)
                ldsm_x4_t(bfr[jn], Bb + (uint32_t)((k0 + a_r) * 272 +
                                                   (n0 + jn * 16 + a_c) * 2));
            #pragma unroll
            for (int im = 0; im < 2; im++)
                #pragma unroll
                for (int jn = 0; jn < 2; jn++) {
                    mma16816h(acc[im][jn * 2 + 0], afr[im], &bfr[jn][0]);
                    mma16816h(acc[im][jn * 2 + 1], afr[im], &bfr[jn][2]);
                }
        }
        uint32_t zb[2] = {0u, 0u};
        if (zcol < 2) {
            const __half* kp = kss + zcol * 128 + k0 + zk;
            zb[0] = *(const uint32_t*)(kp);
            zb[1] = *(const uint32_t*)(kp + 8);
        }
        mma16816h(acc_z[0], afr[0], zb);
        mma16816h(acc_z[1], afr[1], zb);
    }

    const int g = lane >> 2;
    const int t = lane & 3;
    #pragma unroll
    for (int im = 0; im < 2; im++) {
        float den0 = acc_z[im][0] + acc_z[im][1];
        float den1 = acc_z[im][2] + acc_z[im][3];
        den0 = __shfl_sync(0xffffffffu, den0, lane & 28);
        den1 = __shfl_sync(0xffffffffu, den1, lane & 28);
        const float z0 = 8.0f / den0;
        const float z1 = 8.0f / den1;
        const int gr0 = row0 + m0 + im * 16 + g;
        const int gr1 = gr0 + 8;
        #pragma unroll
        for (int j = 0; j < 4; j++) {
            const int col = n0 + j * 8 + t * 2;
            float x0 = acc[im][j][0] * z0;
            float x1 = acc[im][j][1] * z0;
            float x2 = acc[im][j][2] * z1;
            float x3 = acc[im][j][3] * z1;
            x0 = x0 > 0.0f ? x0 : expm1f(x0);
            x1 = x1 > 0.0f ? x1 : expm1f(x1);
            x2 = x2 > 0.0f ? x2 : expm1f(x2);
            x3 = x3 > 0.0f ? x3 : expm1f(x3);
            if (gr0 < NROWS)
                *(float2*)(out + (size_t)gr0 * DOUT + col) = make_float2(x0, x1);
            if (gr1 < NROWS)
                *(float2*)(out + (size_t)gr1 * DOUT + col) = make_float2(x2, x3);
        }
    }
}

// ============================================================================
// Launch
// ============================================================================
extern "C" void kernel_launch(void* const* d_in, const int* in_sizes, int n_in,
                              void* d_out, int out_size)
{
    const float* h  = (const float*)d_in[0];
    const float* Wq = (const float*)d_in[1];
    const float* Wk = (const float*)d_in[2];
    const float* Wv = (const float*)d_in[3];
    float* out = (float*)d_out;

    cudaFuncSetAttribute(qkv_fused, cudaFuncAttributeMaxDynamicSharedMemorySize, SM_QKV_TOTAL);
    cudaFuncSetAttribute(out_mma, cudaFuncAttributeMaxDynamicSharedMemorySize, OUT_SM_TOTAL);

    convert_w<<<(DIN * NQKV + 255) / 256, 256>>>(Wq, Wk, Wv);

    qkv_fused<<<NBLK_M, 512, SM_QKV_TOTAL>>>(h);

    kv_mma<<<NB, 256>>>();

    dim3 gridR1((DOUT * DOUT + DOUT + 255) / 256, 4);
    reduce1<<<gridR1, 256>>>();
    reduce2<<<(DOUT * DOUT + DOUT + 255) / 256, 256>>>();

    out_mma<<<(NROWS + 127) / 128, 512, OUT_SM_TOTAL>>>(out);
}

// round 16
// speedup vs baseline: 1.3475x; 1.0145x over previous
#include <cuda_runtime.h>
#include <cuda_fp16.h>
#include <math.h>
#include <stdint.h>

#define NROWS 200000
#define DIN   512
#define DOUT  128
#define NQKV  384
#define BK    32
#define NCHUNKS (DIN / BK)                    // 16
#define MTILE 128
#define NBLK_M ((NROWS + MTILE - 1) / MTILE)  // 1563

#define CHUNK 704
#define SLABS (CHUNK / 32)                    // 22
#define NB    ((NROWS + CHUNK - 1) / CHUNK)   // 285
#define NB4   ((NB + 3) / 4)                  // 72

#define KV_SCALE_INV  (1.0f / 64.0f)

__device__ __half g_Q[(size_t)NROWS * DOUT];
__device__ __half g_K[(size_t)NROWS * DOUT];
__device__ __half g_V[(size_t)NROWS * DOUT];
__device__ float g_KVpart[(size_t)NB * DOUT * DOUT];
__device__ float g_kspart[(size_t)NB * DOUT];
__device__ float g_sub[4 * (DOUT * DOUT + DOUT)];
__device__ __half g_KVhi[DOUT * DOUT];
__device__ __half g_KVlo[DOUT * DOUT];
__device__ __half g_kshi16[DOUT];
__device__ __half g_kslo16[DOUT];

__device__ __half g_Wh[(size_t)DIN * NQKV];

// ---- qkv smem (BK=32, fused, 3-stage B ring) ----
#define A_ROW_B   80
#define A_STAGE_B (MTILE * A_ROW_B)          // 10240
#define BF_ROW_B  784
#define BF_STAGE_B (BK * BF_ROW_B)           // 25088
#define SM_B_OFF  (2 * A_STAGE_B)            // 20480
#define SM_QKV_TOTAL (SM_B_OFF + 3 * BF_STAGE_B)   // 95744

// ---- kv smem (3-stage ring, dynamic) ----
#define KVT_ROW_B  272
#define KVT_TILE_B (32 * KVT_ROW_B)          // 8704
#define KV_SM_TOTAL (3 * 2 * KVT_TILE_B)     // 52224

#define OUT_Q_OFF   0
#define OUT_Q_B     (128 * 272)
#define OUT_HI_OFF  (OUT_Q_OFF + OUT_Q_B)
#define OUT_KV_B    (128 * 272)
#define OUT_LO_OFF  (OUT_HI_OFF + OUT_KV_B)
#define OUT_KS_OFF  (OUT_LO_OFF + OUT_KV_B)
#define OUT_SM_TOTAL (OUT_KS_OFF + 256 * 2)  // 104960

static __device__ __forceinline__ uint32_t smem_u32(const void* p) {
    uint32_t a;
    asm("{ .reg .u64 t; cvta.to.shared.u64 t, %1; cvt.u32.u64 %0, t; }" : "=r"(a) : "l"(p));
    return a;
}
static __device__ __forceinline__ void cp16(uint32_t dst, const void* src) {
    asm volatile("cp.async.cg.shared.global [%0], [%1], 16;" :: "r"(dst), "l"(src) : "memory");
}
static __device__ __forceinline__ void cp16z(uint32_t dst, const void* src, int sz) {
    asm volatile("cp.async.cg.shared.global [%0], [%1], 16, %2;"
                 :: "r"(dst), "l"(src), "r"(sz) : "memory");
}
#define CP_COMMIT()  asm volatile("cp.async.commit_group;" ::: "memory")
#define CP_WAIT(N)   asm volatile("cp.async.wait_group %0;" :: "n"(N) : "memory")

static __device__ __forceinline__ void ldsm_x4(uint32_t* r, uint32_t addr) {
    asm volatile("ldmatrix.sync.aligned.m8n8.x4.shared.b16 {%0,%1,%2,%3}, [%4];"
                 : "=r"(r[0]), "=r"(r[1]), "=r"(r[2]), "=r"(r[3]) : "r"(addr));
}
static __device__ __forceinline__ void ldsm_x4_t(uint32_t* r, uint32_t addr) {
    asm volatile("ldmatrix.sync.aligned.m8n8.x4.trans.shared.b16 {%0,%1,%2,%3}, [%4];"
                 : "=r"(r[0]), "=r"(r[1]), "=r"(r[2]), "=r"(r[3]) : "r"(addr));
}
static __device__ __forceinline__ void mma16816h(float* d, const uint32_t* a,
                                                 const uint32_t* b) {
    asm volatile(
        "mma.sync.aligned.m16n8k16.row.col.f32.f16.f16.f32 "
        "{%0,%1,%2,%3}, {%4,%5,%6,%7}, {%8,%9}, {%0,%1,%2,%3};"
        : "+f"(d[0]), "+f"(d[1]), "+f"(d[2]), "+f"(d[3])
        : "r"(a[0]), "r"(a[1]), "r"(a[2]), "r"(a[3]), "r"(b[0]), "r"(b[1]));
}

__device__ __forceinline__ float elu_p1(float x) {
    return x > 0.0f ? x + 1.0f : expf(x);
}
static __device__ __forceinline__ uint32_t packh2(float a, float b) {
    __half2 p = __floats2half2_rn(a, b);
    return *(uint32_t*)&p;
}

// ============================================================================
// Kernel W: fp16 weight conversion into [k][384].
// ============================================================================
__global__ void convert_w(const float* __restrict__ Wq,
                          const float* __restrict__ Wk,
                          const float* __restrict__ Wv)
{
    int idx = blockIdx.x * 256 + threadIdx.x;
    if (idx >= DIN * NQKV) return;
    int k = idx / NQKV;
    int n = idx % NQKV;
    const float* W = (n < 128) ? Wq : (n < 256) ? Wk : Wv;
    g_Wh[idx] = __float2half_rn(W[(size_t)k * DOUT + (n & 127)]);
}

// ============================================================================
// Kernel A (fused): [Q|K|V] = f(h @ [Wq|Wk|Wv]) in ONE CTA per m-tile.
// 512 threads, 16 warps (4 wm x 4 wn), warp tile 32x96, BK=32.
// 3-stage B ring: each B load gets 2 chunk-times; CP_WAIT(1) in steady state.
// ============================================================================
__global__ __launch_bounds__(512, 1) void qkv_fused(const float* __restrict__ h)
{
    extern __shared__ __align__(256) unsigned char sm[];
    const uint32_t sbase = smem_u32(sm);

    const int row0  = blockIdx.x * MTILE;
    const int tid   = threadIdx.x;
    const int wid   = tid >> 5;
    const int lane  = tid & 31;

    const int wm = wid & 3;
    const int wn = wid >> 2;
    const int m0 = wm * 32;
    const int n0w = wn * 96;

    const int arow = tid >> 2;
    const int aseg = (tid & 3) * 8;
    int lrow = row0 + arow;
    if (lrow >= NROWS) lrow = NROWS - 1;
    const float* hrow = h + (size_t)lrow * DIN + aseg;
    const uint32_t a_sts_off = (uint32_t)(arow * A_ROW_B + aseg * 2);

    float acc[2][12][4];
    #pragma unroll
    for (int i = 0; i < 2; i++)
        #pragma unroll
        for (int j = 0; j < 12; j++)
            #pragma unroll
            for (int r = 0; r < 4; r++) acc[i][j][r] = 0.0f;

    const int a_r = (lane & 7) + (lane & 8);
    const int a_c = ((lane >> 4) & 1) * 8;
    const int b_k = (lane & 7) + (lane & 8);
    const int b_n = ((lane >> 4) & 1) * 8;

    auto issue_B = [&](int c, int stage) {
        const size_t src_k0 = (size_t)(c * BK) * NQKV;
        uint32_t dstb = sbase + SM_B_OFF + stage * BF_STAGE_B;
        #pragma unroll
        for (int it = 0; it < 3; it++) {
            int idx = tid + it * 512;
            int r = idx / 48, c16 = idx % 48;
            cp16(dstb + r * BF_ROW_B + c16 * 16,
                 g_Wh + src_k0 + (size_t)r * NQKV + c16 * 8);
        }
        CP_COMMIT();
    };
    auto sts_A = [&](int stage, const float4* v) {
        uint32_t hx[4];
        hx[0] = packh2(v[0].x, v[0].y);
        hx[1] = packh2(v[0].z, v[0].w);
        hx[2] = packh2(v[1].x, v[1].y);
        hx[3] = packh2(v[1].z, v[1].w);
        uint32_t dst = sbase + stage * A_STAGE_B + a_sts_off;
        asm volatile("st.shared.v4.b32 [%0], {%1,%2,%3,%4};" :: "r"(dst),
                     "r"(hx[0]),"r"(hx[1]),"r"(hx[2]),"r"(hx[3]));
    };

    float4 v[2];
    v[0] = *(const float4*)(hrow);
    v[1] = *(const float4*)(hrow + 4);
    issue_B(0, 0);
    issue_B(1, 1);
    sts_A(0, v);

    for (int c = 0; c < NCHUNKS; c++) {
        if (c + 1 < NCHUNKS) {
            v[0] = *(const float4*)(hrow + (c + 1) * BK);
            v[1] = *(const float4*)(hrow + (c + 1) * BK + 4);
        }
        // steady state: newest group (B(c+1)) may stay in flight; oldest (B(c)) must land
        if (c + 1 < NCHUNKS) { CP_WAIT(1); } else { CP_WAIT(0); }
        __syncthreads();
        if (c + 2 < NCHUNKS) issue_B(c + 2, (c + 2) % 3);

        const uint32_t Ab = sbase + (c & 1) * A_STAGE_B;
        const uint32_t Bb = sbase + SM_B_OFF + (c % 3) * BF_STAGE_B;
        #pragma unroll
        for (int ks = 0; ks < 2; ks++) {
            const int k0 = ks * 16;
            uint32_t afr[2][4];
            #pragma unroll
            for (int im = 0; im < 2; im++)
                ldsm_x4(afr[im], Ab + (uint32_t)((m0 + im * 16 + a_r) * A_ROW_B +
                                                 (k0 + a_c) * 2));
            #pragma unroll
            for (int hg = 0; hg < 2; hg++) {
                uint32_t bfr[3][4];
                #pragma unroll
                for (int j3 = 0; j3 < 3; j3++)
                    ldsm_x4_t(bfr[j3], Bb + (uint32_t)((k0 + b_k) * BF_ROW_B +
                              (n0w + (hg * 3 + j3) * 16 + b_n) * 2));
                #pragma unroll
                for (int im = 0; im < 2; im++)
                    #pragma unroll
                    for (int j3 = 0; j3 < 3; j3++) {
                        const int j = (hg * 3 + j3) * 2;
                        mma16816h(acc[im][j + 0], afr[im], &bfr[j3][0]);
                        mma16816h(acc[im][j + 1], afr[im], &bfr[j3][2]);
                    }
            }
        }

        if (c + 1 < NCHUNKS) sts_A((c + 1) & 1, v);
    }

    const int g = lane >> 2;
    const int t = lane & 3;

    #pragma unroll
    for (int im = 0; im < 2; im++) {
        const int r0 = row0 + m0 + im * 16 + g;
        const int r1 = r0 + 8;
        #pragma unroll
        for (int j = 0; j < 12; j++) {
            const int col = n0w + j * 8 + t * 2;
            const int which = col >> 7;
            const int lc = col & 127;
            __half* Out = (which == 0) ? g_Q : (which == 1) ? g_K : g_V;
            const bool act = (which < 2);
            float c0 = acc[im][j][0], c1 = acc[im][j][1];
            float c2 = acc[im][j][2], c3 = acc[im][j][3];
            if (act) {
                c0 = elu_p1(c0); c1 = elu_p1(c1);
                c2 = elu_p1(c2); c3 = elu_p1(c3);
            }
            if (r0 < NROWS)
                *(__half2*)(Out + (size_t)r0 * DOUT + lc) = __floats2half2_rn(c0, c1);
            if (r1 < NROWS)
                *(__half2*)(Out + (size_t)r1 * DOUT + lc) = __floats2half2_rn(c2, c3);
        }
    }
}

// ============================================================================
// Kernel B: partial KV = K_chunk^T @ V_chunk via fp16 mma + k_sum via MMA.
// CHUNK=704 -> 285 blocks (single wave @ occ 2). 3-stage cp.async ring.
// ============================================================================
__global__ __launch_bounds__(256, 2) void kv_mma()
{
    extern __shared__ __align__(16) unsigned char smkv[];
    const uint32_t sb = smem_u32(smkv);

    const int tid  = threadIdx.x;
    const int wid  = tid >> 5;
    const int lane = tid & 31;
    const int m0 = (wid & 3) * 32;
    const int n0 = (wid >> 2) * 64;
    const int wn = wid >> 2;
    const int base = blockIdx.x * CHUNK;

    float acc[2][8][4];
    #pragma unroll
    for (int i = 0; i < 2; i++)
        #pragma unroll
        for (int j = 0; j < 8; j++)
            #pragma unroll
            for (int r = 0; r < 4; r++) acc[i][j][r] = 0.0f;
    float acc_ks[2][4];
    #pragma unroll
    for (int i = 0; i < 2; i++)
        #pragma unroll
        for (int r = 0; r < 4; r++) acc_ks[i][r] = 0.0f;

    const uint32_t b_ones[2] = {0x3C003C00u, 0x3C003C00u};

    auto issue = [&](int it, int stage) {
        #pragma unroll
        for (int q = 0; q < 4; q++) {
            int idx  = tid + q * 256;
            int tile = idx >> 9;
            int row  = (idx >> 4) & 31;
            int c16  = idx & 15;
            int grow = base + it * 32 + row;
            const __half* src = (tile ? g_V : g_K) + (size_t)grow * DOUT + c16 * 8;
            uint32_t dst = sb + stage * 2 * KVT_TILE_B + tile * KVT_TILE_B +
                           row * KVT_ROW_B + c16 * 16;
            cp16z(dst, src, (grow < NROWS) ? 16 : 0);
        }
        CP_COMMIT();
    };

    const int trow = (lane & 7) + (lane & 8);
    const int tcol = ((lane >> 4) & 1) * 8;

    issue(0, 0);
    issue(1, 1);

    for (int it = 0; it < SLABS; it++) {
        if (it + 1 < SLABS) { CP_WAIT(1); } else { CP_WAIT(0); }
        __syncthreads();
        if (it + 2 < SLABS) issue(it + 2, (it + 2) % 3);

        const uint32_t Kb = sb + (it % 3) * 2 * KVT_TILE_B;
        const uint32_t Vb = Kb + KVT_TILE_B;

        #pragma unroll
        for (int ks = 0; ks < 2; ks++) {
            const int k0 = ks * 16;
            uint32_t afr[2][4];
            #pragma unroll
            for (int im = 0; im < 2; im++) {
                uint32_t t4[4];
                ldsm_x4_t(t4, Kb + (uint32_t)((k0 + trow) * KVT_ROW_B +
                                              (m0 + im * 16 + tcol) * 2));
                afr[im][0] = t4[0]; afr[im][1] = t4[2];
                afr[im][2] = t4[1]; afr[im][3] = t4[3];
            }
            uint32_t bfr[4][4];
            #pragma unroll
            for (int jn = 0; jn < 4; jn++)
                ldsm_x4_t(bfr[jn], Vb + (uint32_t)((k0 + trow) * KVT_ROW_B +
                                                   (n0 + jn * 16 + tcol) * 2));
            #pragma unroll
            for (int im = 0; im < 2; im++)
                #pragma unroll
                for (int jn = 0; jn < 4; jn++) {
                    mma16816h(acc[im][jn * 2 + 0], afr[im], &bfr[jn][0]);
                    mma16816h(acc[im][jn * 2 + 1], afr[im], &bfr[jn][2]);
                }
            if (wn == 0) {
                mma16816h(acc_ks[0], afr[0], b_ones);
                mma16816h(acc_ks[1], afr[1], b_ones);
            }
        }
    }

    float* kvout = g_KVpart + (size_t)blockIdx.x * (DOUT * DOUT);
    const int g = lane >> 2;
    const int t = lane & 3;
    #pragma unroll
    for (int im = 0; im < 2; im++) {
        const int r0 = m0 + im * 16 + g;
        #pragma unroll
        for (int j = 0; j < 8; j++) {
            const int col = n0 + j * 8 + t * 2;
            *(float2*)(kvout + (size_t)r0 * DOUT + col) =
                make_float2(acc[im][j][0], acc[im][j][1]);
            *(float2*)(kvout + (size_t)(r0 + 8) * DOUT + col) =
                make_float2(acc[im][j][2], acc[im][j][3]);
        }
    }
    if (wn == 0 && t == 0) {
        #pragma unroll
        for (int im = 0; im < 2; im++) {
            const int r = m0 + im * 16 + g;
            g_kspart[(size_t)blockIdx.x * DOUT + r]     = acc_ks[im][0];
            g_kspart[(size_t)blockIdx.x * DOUT + r + 8] = acc_ks[im][2];
        }
    }
}

// ============================================================================
// Reduce phase 1: 4 sub-range partial sums. Grid (65, 4).
// ============================================================================
__global__ void reduce1()
{
    const int sub = blockIdx.y;
    const int i = blockIdx.x * blockDim.x + threadIdx.x;
    if (i >= DOUT * DOUT + DOUT) return;
    const int b0 = sub * NB4;
    const int b1 = (b0 + NB4 < NB) ? b0 + NB4 : NB;

    float s0 = 0.0f, s1 = 0.0f, s2 = 0.0f, s3 = 0.0f;
    if (i < DOUT * DOUT) {
        int b = b0;
        for (; b + 3 < b1; b += 4) {
            s0 += g_KVpart[(size_t)(b + 0) * (DOUT * DOUT) + i];
            s1 += g_KVpart[(size_t)(b + 1) * (DOUT * DOUT) + i];
            s2 += g_KVpart[(size_t)(b + 2) * (DOUT * DOUT) + i];
            s3 += g_KVpart[(size_t)(b + 3) * (DOUT * DOUT) + i];
        }
        for (; b < b1; b++) s0 += g_KVpart[(size_t)b * (DOUT * DOUT) + i];
    } else {
        const int j = i - DOUT * DOUT;
        int b = b0;
        for (; b + 3 < b1; b += 4) {
            s0 += g_kspart[(size_t)(b + 0) * DOUT + j];
            s1 += g_kspart[(size_t)(b + 1) * DOUT + j];
            s2 += g_kspart[(size_t)(b + 2) * DOUT + j];
            s3 += g_kspart[(size_t)(b + 3) * DOUT + j];
        }
        for (; b < b1; b++) s0 += g_kspart[(size_t)b * DOUT + j];
    }
    g_sub[sub * (DOUT * DOUT + DOUT) + i] = ((s0 + s1) + (s2 + s3));
}

// ============================================================================
// Reduce phase 2: combine 4 subs, emit fp16 hi/lo KV and ksum.
// ============================================================================
__global__ void reduce2()
{
    const int i = blockIdx.x * blockDim.x + threadIdx.x;
    if (i >= DOUT * DOUT + DOUT) return;
    const int stride = DOUT * DOUT + DOUT;
    float s = (g_sub[i] + g_sub[stride + i]) +
              (g_sub[2 * stride + i] + g_sub[3 * stride + i]);
    if (i < DOUT * DOUT) {
        s *= KV_SCALE_INV;
        __half hi = __float2half_rn(s);
        g_KVhi[i] = hi;
        g_KVlo[i] = __float2half_rn(s - __half2float(hi));
    } else {
        const int j = i - DOUT * DOUT;
        s *= 0.125f;
        __half hi = __float2half_rn(s);
        g_kshi16[j] = hi;
        g_kslo16[j] = __float2half_rn(s - __half2float(hi));
    }
}

// ============================================================================
// Kernel C: out = elu((Q @ KV) / (Q @ ksum)) via fp16 mma. 128-row blocks.
// ============================================================================
__global__ __launch_bounds__(512, 1) void out_mma(float* __restrict__ out)
{
    extern __shared__ __align__(256) unsigned char smo[];
    const uint32_t sb = smem_u32(smo);

    const int tid  = threadIdx.x;
    const int wid  = tid >> 5;
    const int lane = tid & 31;
    const int row0 = blockIdx.x * 128;

    const int m0 = (wid & 3) * 32;
    const int n0 = (wid >> 2) * 32;

    #pragma unroll
    for (int q = 0; q < 4; q++) {
        int idx = tid + q * 512;
        int r = idx >> 4, c16 = idx & 15;
        int grow = row0 + r;
        cp16z(sb + OUT_Q_OFF + r * 272 + c16 * 16,
              g_Q + (size_t)grow * DOUT + c16 * 8,
              (grow < NROWS) ? 16 : 0);
    }
    #pragma unroll
    for (int q = 0; q < 8; q++) {
        int idx = tid + q * 512;
        int part = idx >> 11;
        int rem = idx & 2047;
        int r = rem >> 4, c16 = rem & 15;
        const __half* src = (part ? g_KVlo : g_KVhi) + r * DOUT + c16 * 8;
        cp16(sb + (part ? OUT_LO_OFF : OUT_HI_OFF) + r * 272 + c16 * 16, src);
    }
    CP_COMMIT();
    __half* kss = (__half*)(smo + OUT_KS_OFF);
    if (tid < 128) kss[tid] = g_kshi16[tid];
    else if (tid < 256) kss[tid] = g_kslo16[tid - 128];
    CP_WAIT(0);
    __syncthreads();

    float acc[2][4][4];
    #pragma unroll
    for (int i = 0; i < 2; i++)
        #pragma unroll
        for (int j = 0; j < 4; j++)
            #pragma unroll
            for (int r = 0; r < 4; r++) acc[i][j][r] = 0.0f;
    float acc_z[2][4];
    #pragma unroll
    for (int i = 0; i < 2; i++)
        #pragma unroll
        for (int r = 0; r < 4; r++) acc_z[i][r] = 0.0f;

    const int a_r = (lane & 7) + (lane & 8);
    const int a_c = ((lane >> 4) & 1) * 8;
    const int zcol = lane >> 2;
    const int zk   = (lane & 3) * 2;

    #pragma unroll
    for (int ks = 0; ks < 8; ks++) {
        const int k0 = ks * 16;
        uint32_t afr[2][4];
        #pragma unroll
        for (int im = 0; im < 2; im++)
            ldsm_x4(afr[im], sb + OUT_Q_OFF +
                    (uint32_t)((m0 + im * 16 + a_r) * 272 + (k0 + a_c) * 2));
        #pragma unroll
        for (int part = 0; part < 2; part++) {
            const uint32_t Bb = sb + (part ? OUT_LO_OFF : OUT_HI_OFF);
            uint32_t bfr[2][4];
            #pragma unroll
            for (int jn = 0; jn < 2; jn++)
                ldsm_x4_t(bfr[jn], Bb + (uint32_t)((k0 + a_r) * 272 +
                                                   (n0 + jn * 16 + a_c) * 2));
            #pragma unroll
            for (int im = 0; im < 2; im++)
                #pragma unroll
                for (int jn = 0; jn < 2; jn++) {
                    mma16816h(acc[im][jn * 2 + 0], afr[im], &bfr[jn][0]);
                    mma16816h(acc[im][jn * 2 + 1], afr[im], &bfr[jn][2]);
                }
        }
        uint32_t zb[2] = {0u, 0u};
        if (zcol < 2) {
            const __half* kp = kss + zcol * 128 + k0 + zk;
            zb[0] = *(const uint32_t*)(kp);
            zb[1] = *(const uint32_t*)(kp + 8);
        }
        mma16816h(acc_z[0], afr[0], zb);
        mma16816h(acc_z[1], afr[1], zb);
    }

    const int g = lane >> 2;
    const int t = lane & 3;
    #pragma unroll
    for (int im = 0; im < 2; im++) {
        float den0 = acc_z[im][0] + acc_z[im][1];
        float den1 = acc_z[im][2] + acc_z[im][3];
        den0 = __shfl_sync(0xffffffffu, den0, lane & 28);
        den1 = __shfl_sync(0xffffffffu, den1, lane & 28);
        const float z0 = 8.0f / den0;
        const float z1 = 8.0f / den1;
        const int gr0 = row0 + m0 + im * 16 + g;
        const int gr1 = gr0 + 8;
        #pragma unroll
        for (int j = 0; j < 4; j++) {
            const int col = n0 + j * 8 + t * 2;
            float x0 = acc[im][j][0] * z0;
            float x1 = acc[im][j][1] * z0;
            float x2 = acc[im][j][2] * z1;
            float x3 = acc[im][j][3] * z1;
            x0 = x0 > 0.0f ? x0 : expm1f(x0);
            x1 = x1 > 0.0f ? x1 : expm1f(x1);
            x2 = x2 > 0.0f ? x2 : expm1f(x2);
            x3 = x3 > 0.0f ? x3 : expm1f(x3);
            if (gr0 < NROWS)
                *(float2*)(out + (size_t)gr0 * DOUT + col) = make_float2(x0, x1);
            if (gr1 < NROWS)
                *(float2*)(out + (size_t)gr1 * DOUT + col) = make_float2(x2, x3);
        }
    }
}

// ============================================================================
// Launch
// ============================================================================
extern "C" void kernel_launch(void* const* d_in, const int* in_sizes, int n_in,
                              void* d_out, int out_size)
{
    const float* h  = (const float*)d_in[0];
    const float* Wq = (const float*)d_in[1];
    const float* Wk = (const float*)d_in[2];
    const float* Wv = (const float*)d_in[3];
    float* out = (float*)d_out;

    cudaFuncSetAttribute(qkv_fused, cudaFuncAttributeMaxDynamicSharedMemorySize, SM_QKV_TOTAL);
    cudaFuncSetAttribute(kv_mma, cudaFuncAttributeMaxDynamicSharedMemorySize, KV_SM_TOTAL);
    cudaFuncSetAttribute(out_mma, cudaFuncAttributeMaxDynamicSharedMemorySize, OUT_SM_TOTAL);

    convert_w<<<(DIN * NQKV + 255) / 256, 256>>>(Wq, Wk, Wv);

    qkv_fused<<<NBLK_M, 512, SM_QKV_TOTAL>>>(h);

    kv_mma<<<NB, 256, KV_SM_TOTAL>>>();

    dim3 gridR1((DOUT * DOUT + DOUT + 255) / 256, 4);
    reduce1<<<gridR1, 256>>>();
    reduce2<<<(DOUT * DOUT + DOUT + 255) / 256, 256>>>();

    out_mma<<<(NROWS + 127) / 128, 512, OUT_SM_TOTAL>>>(out);
}